// round 2
// baseline (speedup 1.0000x reference)
#include <cuda_runtime.h>
#include <math.h>

typedef unsigned long long ull;

#define V_VOCAB 50257
#define VPAD    51200          // 20 chunks * 2560
#define NCHUNK  20
#define VCHUNK  2560
#define HID     512
#define NB      32
#define TT      128
#define NSTEP   127
#define NROWS   4064           // NSTEP * NB

// ---------------- static device scratch (no runtime allocation) ----------------
__device__ __align__(16) float g_Wt_emit[512 * VPAD];       // emit_W transposed [k][v], zero padded
__device__ __align__(16) float g_Wt_ih[512 * 1536];         // W_ih transposed [k][j]
__device__ __align__(16) float g_Git[(size_t)NSTEP * 1536 * NB]; // gi, layout [t][j][n]
__device__ __align__(16) float g_Hst[128 * HID * NB];       // hidden states, [t][k][n]; slot0=init, slot t+1 = after step t
__device__ float g_Pm[NCHUNK * NROWS];                      // per-chunk running max
__device__ float g_Ps[NCHUNK * NROWS];                      // per-chunk sum of exp
__device__ float g_Tlog[NROWS];                             // target logits

// ---------------- f32x2 helpers (Blackwell packed fp32 FMA) ----------------
__device__ __forceinline__ ull pack2(float lo, float hi) {
    ull r; asm("mov.b64 %0, {%1, %2};" : "=l"(r) : "f"(lo), "f"(hi)); return r;
}
__device__ __forceinline__ float2 unpack2(ull v) {
    float2 f; asm("mov.b64 {%0, %1}, %2;" : "=f"(f.x), "=f"(f.y) : "l"(v)); return f;
}
__device__ __forceinline__ void ffma2(ull& acc, ull a, ull b) {
    asm("fma.rn.f32x2 %0, %1, %2, %0;" : "+l"(acc) : "l"(a), "l"(b));
}

__device__ __forceinline__ float sigmoidf_(float x) { return 1.0f / (1.0f + expf(-x)); }

__device__ __forceinline__ void lse_update(float& m, float& s, float x) {
    if (x > m) { s = s * __expf(m - x) + 1.0f; m = x; }
    else       { s += __expf(x - m); }
}
__device__ __forceinline__ void lse_combine(float& M, float& S, float m2, float s2) {
    if (m2 > M) { S = S * expf(M - m2) + s2; M = m2; }
    else        { S += s2 * expf(m2 - M); }
}

// ---------------- transpose: src[r][c] (c=512 wide) -> dst[c][r], zero-pad r>=Rvalid ----------------
__global__ void transposeK(const float* __restrict__ src, int Rvalid, int Rpad, int sel) {
    float* dst = sel ? g_Wt_ih : g_Wt_emit;
    __shared__ float tile[32][33];
    int r0 = blockIdx.x * 32, c0 = blockIdx.y * 32;
    int tx = threadIdx.x, ty = threadIdx.y;
#pragma unroll
    for (int dy = 0; dy < 32; dy += 8) {
        int r = r0 + ty + dy;
        tile[ty + dy][tx] = (r < Rvalid) ? src[(size_t)r * 512 + c0 + tx] : 0.0f;
    }
    __syncthreads();
#pragma unroll
    for (int dy = 0; dy < 32; dy += 8) {
        dst[(size_t)(c0 + ty + dy) * Rpad + r0 + tx] = tile[tx][ty + dy];
    }
}

// ---------------- init: Hst[0][k][n] = h0[n][k] ----------------
__global__ void initK(const float* __restrict__ h0) {
    int idx = blockIdx.x * blockDim.x + threadIdx.x;   // 0..16383
    int n = idx >> 9, k = idx & 511;
    g_Hst[k * NB + n] = h0[idx];
}

// ---------------- gi GEMM: Git[t][j][n] = embed_W[words[n][t]] . W_ih[j] + b_ih[j] ----------------
// block: 16 rows(t,n) x 512 j; thread tile 4 rows x 8 j (4 f32x2 pairs)
__global__ __launch_bounds__(256) void giK(const int* __restrict__ words,
                                           const float* __restrict__ embW,
                                           const float* __restrict__ b_ih) {
    int jc = blockIdx.x;      // 0..2  (j chunk of 512)
    int rg = blockIdx.y;      // 0..253 (row group of 16)
    int tid = threadIdx.x, tx = tid & 63, ty = tid >> 6;
    __shared__ float ash[16 * 514];
    int rbase = rg * 16;
    for (int idx = tid; idx < 8192; idx += 256) {
        int i = idx >> 9, k = idx & 511;
        int r = rbase + i;
        int w = words[(r & 31) * TT + (r >> 5)];
        ash[i * 514 + k] = embW[(size_t)w * 512 + k];
    }
    __syncthreads();

    int j0 = jc * 512 + tx * 8;
    ull acc[4][4];
#pragma unroll
    for (int a = 0; a < 4; ++a)
#pragma unroll
        for (int b = 0; b < 4; ++b) acc[a][b] = 0ull;

    const float* wp = g_Wt_ih + j0;
    int rb = ty * 4;
#pragma unroll 4
    for (int k = 0; k < 512; ++k) {
        float4 wa = *(const float4*)(wp);
        float4 wb = *(const float4*)(wp + 4);
        wp += 1536;
        ull b0 = pack2(wa.x, wa.y), b1 = pack2(wa.z, wa.w);
        ull b2 = pack2(wb.x, wb.y), b3 = pack2(wb.z, wb.w);
#pragma unroll
        for (int ri = 0; ri < 4; ++ri) {
            float h = ash[(rb + ri) * 514 + k];
            ull a2 = pack2(h, h);
            ffma2(acc[ri][0], a2, b0);
            ffma2(acc[ri][1], a2, b1);
            ffma2(acc[ri][2], a2, b2);
            ffma2(acc[ri][3], a2, b3);
        }
    }

    int t = rbase >> 5;
#pragma unroll
    for (int ri = 0; ri < 4; ++ri) {
        int r = rbase + rb + ri;
        int n = r & 31;
#pragma unroll
        for (int p = 0; p < 4; ++p) {
            float2 l = unpack2(acc[ri][p]);
            int j = j0 + 2 * p;
            g_Git[((size_t)t * 1536 + j) * NB + n]     = l.x + b_ih[j];
            g_Git[((size_t)t * 1536 + j + 1) * NB + n] = l.y + b_ih[j + 1];
        }
    }
}

// ---------------- sequential GRU step: reads Hst[t], Git[t]; writes Hst[t+1] ----------------
// grid 128 blocks x 128 threads: thread = (j = bx*4 + tid/32, n = tid%32)
__global__ __launch_bounds__(128) void stepK(const float* __restrict__ W_hh,
                                             const float* __restrict__ b_hh, int t) {
    int tid = threadIdx.x;
    int n = tid & 31, jy = tid >> 5;
    int j = blockIdx.x * 4 + jy;

    const float* hp = g_Hst + (size_t)t * (HID * NB);   // [k][n]
    const float* wr = W_hh + (size_t)j * 512;
    const float* wz = wr + 512 * 512;
    const float* wn = wz + 512 * 512;

    float ar = 0.f, az = 0.f, an = 0.f;
#pragma unroll 4
    for (int k = 0; k < 512; k += 4) {
        float4 r4 = *(const float4*)(wr + k);
        float4 z4 = *(const float4*)(wz + k);
        float4 n4 = *(const float4*)(wn + k);
        float h0 = hp[(k + 0) * NB + n];
        float h1 = hp[(k + 1) * NB + n];
        float h2 = hp[(k + 2) * NB + n];
        float h3 = hp[(k + 3) * NB + n];
        ar = fmaf(r4.x, h0, fmaf(r4.y, h1, fmaf(r4.z, h2, fmaf(r4.w, h3, ar))));
        az = fmaf(z4.x, h0, fmaf(z4.y, h1, fmaf(z4.z, h2, fmaf(z4.w, h3, az))));
        an = fmaf(n4.x, h0, fmaf(n4.y, h1, fmaf(n4.z, h2, fmaf(n4.w, h3, an))));
    }

    float gr = g_Git[((size_t)t * 1536 + j) * NB + n];
    float gz = g_Git[((size_t)t * 1536 + j + 512) * NB + n];
    float gn = g_Git[((size_t)t * 1536 + j + 1024) * NB + n];

    float hr = ar + b_hh[j];
    float hz = az + b_hh[j + 512];
    float hn = an + b_hh[j + 1024];

    float rg_ = sigmoidf_(gr + hr);
    float zg  = sigmoidf_(gz + hz);
    float ng  = tanhf(gn + rg_ * hn);
    float hprev = hp[j * NB + n];
    g_Hst[(size_t)(t + 1) * (HID * NB) + j * NB + n] = (1.0f - zg) * ng + zg * hprev;
}

// ---------------- fused emit GEMM + online logsumexp over vocab chunks ----------------
// grid (chunk 0..19, rowgroup 0..253); block 256 = 4(ty: row groups of 4) x 64(tx)
// thread tile: 4 rows x 8 vocab (4 f32x2 pairs); block covers 16 rows x 2560 vocab (5 iters of 512)
__global__ __launch_bounds__(256) void emitK(const float* __restrict__ emit_b) {
    int chunk = blockIdx.x;
    int rg = blockIdx.y;
    int tid = threadIdx.x, tx = tid & 63, ty = tid >> 6;

    __shared__ float hsh[16 * 514];
    __shared__ float redm[16 * 64];
    __shared__ float reds[16 * 64];

    int t = rg >> 1;
    int n0 = (rg & 1) * 16;
    const float* hsrc = g_Hst + (size_t)(t + 1) * (HID * NB) + n0;   // h after step t
    for (int idx = tid; idx < 8192; idx += 256) {
        int i = idx & 15, k = idx >> 4;
        hsh[i * 514 + k] = hsrc[k * NB + i];
    }
    __syncthreads();

    int rb = ty * 4;
    float mrun[4], srun[4];
#pragma unroll
    for (int ri = 0; ri < 4; ++ri) { mrun[ri] = -1e30f; srun[ri] = 0.0f; }

    for (int it = 0; it < 5; ++it) {
        int v0 = chunk * VCHUNK + it * 512 + tx * 8;
        ull acc[4][4];
#pragma unroll
        for (int a = 0; a < 4; ++a)
#pragma unroll
            for (int b = 0; b < 4; ++b) acc[a][b] = 0ull;

        const float* wp = g_Wt_emit + v0;
#pragma unroll 4
        for (int k = 0; k < 512; ++k) {
            float4 wa = *(const float4*)(wp);
            float4 wb = *(const float4*)(wp + 4);
            wp += VPAD;
            ull b0 = pack2(wa.x, wa.y), b1 = pack2(wa.z, wa.w);
            ull b2 = pack2(wb.x, wb.y), b3 = pack2(wb.z, wb.w);
#pragma unroll
            for (int ri = 0; ri < 4; ++ri) {
                float h = hsh[(rb + ri) * 514 + k];
                ull a2 = pack2(h, h);
                ffma2(acc[ri][0], a2, b0);
                ffma2(acc[ri][1], a2, b1);
                ffma2(acc[ri][2], a2, b2);
                ffma2(acc[ri][3], a2, b3);
            }
        }
        // fold this 8-vocab strip into running (max, sumexp)
#pragma unroll
        for (int ri = 0; ri < 4; ++ri) {
#pragma unroll
            for (int p = 0; p < 4; ++p) {
                float2 l = unpack2(acc[ri][p]);
                int v = v0 + 2 * p;
                if (v < V_VOCAB)     lse_update(mrun[ri], srun[ri], l.x + emit_b[v]);
                if (v + 1 < V_VOCAB) lse_update(mrun[ri], srun[ri], l.y + emit_b[v + 1]);
            }
        }
    }

    // block reduction across tx (64 partials per row)
#pragma unroll
    for (int ri = 0; ri < 4; ++ri) {
        redm[(rb + ri) * 64 + tx] = mrun[ri];
        reds[(rb + ri) * 64 + tx] = srun[ri];
    }
    __syncthreads();
    if (tid < 16) {
        float M = -1e30f, S = 0.0f;
        for (int x = 0; x < 64; ++x) lse_combine(M, S, redm[tid * 64 + x], reds[tid * 64 + x]);
        int r = rg * 16 + tid;
        g_Pm[chunk * NROWS + r] = M;
        g_Ps[chunk * NROWS + r] = S;
    }
}

// ---------------- target logits: one warp per (t, n) row ----------------
__global__ void tlogK(const int* __restrict__ words,
                      const float* __restrict__ emit_W,
                      const float* __restrict__ emit_b) {
    int gtid = blockIdx.x * blockDim.x + threadIdx.x;
    int warp = gtid >> 5;
    int lane = threadIdx.x & 31;
    if (warp >= NROWS) return;
    int t = warp >> 5, n = warp & 31;
    int tgt = words[n * TT + t + 1];
    const float* h = g_Hst + (size_t)(t + 1) * (HID * NB);
    const float* w = emit_W + (size_t)tgt * 512;
    float s = 0.0f;
    for (int k = lane; k < 512; k += 32) s += h[k * NB + n] * w[k];
#pragma unroll
    for (int o = 16; o; o >>= 1) s += __shfl_xor_sync(0xffffffffu, s, o);
    if (lane == 0) g_Tlog[warp] = s + emit_b[tgt];
}

// ---------------- finalize: emit_marginal[n] = sum_t (tlog - lse) / 127 ----------------
__global__ void finK(float* __restrict__ out) {
    int n = blockIdx.x;
    int tid = threadIdx.x;
    __shared__ float sh[128];
    float v = 0.0f;
    if (tid < NSTEP) {
        int r = tid * NB + n;
        float M = -1e30f, S = 0.0f;
        for (int c = 0; c < NCHUNK; ++c) lse_combine(M, S, g_Pm[c * NROWS + r], g_Ps[c * NROWS + r]);
        v = g_Tlog[r] - (M + logf(S));
    }
    sh[tid] = v;
    __syncthreads();
    for (int o = 64; o; o >>= 1) { if (tid < o) sh[tid] += sh[tid + o]; __syncthreads(); }
    if (tid == 0) out[n] = sh[0] / (float)NSTEP;
}

// ---------------- h_final: out[32 + n*512 + k] = Hst[127][k][n] ----------------
__global__ void hfinK(float* __restrict__ out) {
    int idx = blockIdx.x * blockDim.x + threadIdx.x;  // 0..16383
    int n = idx >> 9, k = idx & 511;
    out[32 + idx] = g_Hst[(size_t)127 * (HID * NB) + k * NB + n];
}

// ---------------- launch ----------------
extern "C" void kernel_launch(void* const* d_in, const int* in_sizes, int n_in,
                              void* d_out, int out_size) {
    const int*   words  = (const int*)d_in[0];
    const float* h0     = (const float*)d_in[1];
    const float* embW   = (const float*)d_in[2];
    const float* W_ih   = (const float*)d_in[3];
    const float* W_hh   = (const float*)d_in[4];
    const float* b_ih   = (const float*)d_in[5];
    const float* b_hh   = (const float*)d_in[6];
    const float* emit_W = (const float*)d_in[7];
    const float* emit_b = (const float*)d_in[8];
    float* out = (float*)d_out;

    // transposes (independent prep)
    transposeK<<<dim3(VPAD / 32, 16), dim3(32, 8)>>>(emit_W, V_VOCAB, VPAD, 0);
    transposeK<<<dim3(1536 / 32, 16), dim3(32, 8)>>>(W_ih, 1536, 1536, 1);

    // initial hidden state (transposed)
    initK<<<64, 256>>>(h0);

    // all input-gate projections in parallel
    giK<<<dim3(3, 254), 256>>>(words, embW, b_ih);

    // sequential GRU recurrence
    for (int t = 0; t < NSTEP; ++t)
        stepK<<<128, 128>>>(W_hh, b_hh, t);

    // fused emit GEMM + logsumexp
    emitK<<<dim3(NCHUNK, 254), 256>>>(emit_b);

    // target logits
    tlogK<<<508, 256>>>(words, emit_W, emit_b);

    // reductions + outputs
    finK<<<32, 128>>>(out);
    hfinK<<<64, 256>>>(out);
}

// round 3
// speedup vs baseline: 2.1834x; 2.1834x over previous
#include <cuda_runtime.h>
#include <math.h>

typedef unsigned long long ull;

#define V_VOCAB 50257
#define VPAD    51200          // 400 vocab tiles * 128
#define NVT     400            // vocab tiles
#define VT      128            // vocab per tile
#define HID     512
#define NB      32
#define TT      128
#define NSTEP   127
#define NROWS   4064           // NSTEP * NB

// ---------------- static device scratch ----------------
__device__ __align__(16) float g_Wt_emit[512 * VPAD];       // emit_W transposed [k][v], zero padded
__device__ __align__(16) float g_Wt_ih[512 * 1536];         // W_ih transposed [k][j]
__device__ __align__(16) float g_Git[(size_t)NSTEP * 1536 * NB]; // gi, [t][j][n]
__device__ __align__(16) float g_Hst[128 * HID * NB];       // hidden states [t][k][n]
__device__ __align__(16) float g_bpad[VPAD];                // emit_b padded with -1e30
__device__ float g_Pm[(size_t)NVT * NROWS];                 // per-vocab-tile running max
__device__ float g_Ps[(size_t)NVT * NROWS];                 // per-vocab-tile sum of exp
__device__ float g_Tlog[NROWS];                             // target logits

// ---------------- f32x2 helpers ----------------
__device__ __forceinline__ ull pack2(float lo, float hi) {
    ull r; asm("mov.b64 %0, {%1, %2};" : "=l"(r) : "f"(lo), "f"(hi)); return r;
}
__device__ __forceinline__ float2 unpack2(ull v) {
    float2 f; asm("mov.b64 {%0, %1}, %2;" : "=f"(f.x), "=f"(f.y) : "l"(v)); return f;
}
__device__ __forceinline__ void ffma2(ull& acc, ull a, ull b) {
    asm("fma.rn.f32x2 %0, %1, %2, %0;" : "+l"(acc) : "l"(a), "l"(b));
}

__device__ __forceinline__ float sigmoidf_(float x) { return 1.0f / (1.0f + expf(-x)); }

__device__ __forceinline__ void lse_combine(float& M, float& S, float m2, float s2) {
    if (m2 > M) { S = S * expf(M - m2) + s2; M = m2; }
    else        { S += s2 * expf(m2 - M); }
}

// ---------------- transpose: src[r][c] (c=512) -> dst[c][r], zero-pad r>=Rvalid ----------------
__global__ void transposeK(const float* __restrict__ src, int Rvalid, int Rpad, int sel) {
    float* dst = sel ? g_Wt_ih : g_Wt_emit;
    __shared__ float tile[32][33];
    int r0 = blockIdx.x * 32, c0 = blockIdx.y * 32;
    int tx = threadIdx.x, ty = threadIdx.y;
#pragma unroll
    for (int dy = 0; dy < 32; dy += 8) {
        int r = r0 + ty + dy;
        tile[ty + dy][tx] = (r < Rvalid) ? src[(size_t)r * 512 + c0 + tx] : 0.0f;
    }
    __syncthreads();
#pragma unroll
    for (int dy = 0; dy < 32; dy += 8) {
        dst[(size_t)(c0 + ty + dy) * Rpad + r0 + tx] = tile[tx][ty + dy];
    }
}

// ---------------- init hidden (transposed) + padded bias ----------------
__global__ void initK(const float* __restrict__ h0) {
    int idx = blockIdx.x * blockDim.x + threadIdx.x;   // 0..16383
    int n = idx >> 9, k = idx & 511;
    g_Hst[k * NB + n] = h0[idx];
}
__global__ void bpadK(const float* __restrict__ emit_b) {
    int v = blockIdx.x * blockDim.x + threadIdx.x;
    if (v < VPAD) g_bpad[v] = (v < V_VOCAB) ? emit_b[v] : -1e30f;
}

// ---------------- gi GEMM: Git[t][j][n] = embed_W[words[n][t]] . W_ih[j] + b_ih[j] ----------------
__global__ __launch_bounds__(256) void giK(const int* __restrict__ words,
                                           const float* __restrict__ embW,
                                           const float* __restrict__ b_ih) {
    int jc = blockIdx.x;      // 0..2
    int rg = blockIdx.y;      // 0..253
    int tid = threadIdx.x, tx = tid & 63, ty = tid >> 6;
    __shared__ float ash[16 * 514];
    int rbase = rg * 16;
    for (int idx = tid; idx < 8192; idx += 256) {
        int i = idx >> 9, k = idx & 511;
        int r = rbase + i;
        int w = words[(r & 31) * TT + (r >> 5)];
        ash[i * 514 + k] = embW[(size_t)w * 512 + k];
    }
    __syncthreads();

    int j0 = jc * 512 + tx * 8;
    ull acc[4][4];
#pragma unroll
    for (int a = 0; a < 4; ++a)
#pragma unroll
        for (int b = 0; b < 4; ++b) acc[a][b] = 0ull;

    const float* wp = g_Wt_ih + j0;
    int rb = ty * 4;
#pragma unroll 4
    for (int k = 0; k < 512; ++k) {
        float4 wa = *(const float4*)(wp);
        float4 wb = *(const float4*)(wp + 4);
        wp += 1536;
        ull b0 = pack2(wa.x, wa.y), b1 = pack2(wa.z, wa.w);
        ull b2 = pack2(wb.x, wb.y), b3 = pack2(wb.z, wb.w);
#pragma unroll
        for (int ri = 0; ri < 4; ++ri) {
            float h = ash[(rb + ri) * 514 + k];
            ull a2 = pack2(h, h);
            ffma2(acc[ri][0], a2, b0);
            ffma2(acc[ri][1], a2, b1);
            ffma2(acc[ri][2], a2, b2);
            ffma2(acc[ri][3], a2, b3);
        }
    }

    int t = rbase >> 5;
#pragma unroll
    for (int ri = 0; ri < 4; ++ri) {
        int r = rbase + rb + ri;
        int n = r & 31;
#pragma unroll
        for (int p = 0; p < 4; ++p) {
            float2 l = unpack2(acc[ri][p]);
            int j = j0 + 2 * p;
            g_Git[((size_t)t * 1536 + j) * NB + n]     = l.x + b_ih[j];
            g_Git[((size_t)t * 1536 + j + 1) * NB + n] = l.y + b_ih[j + 1];
        }
    }
}

// ---------------- sequential GRU step, split-k x4 ----------------
// grid 128 blocks x 512 threads: thread = (j = bx*4 + tid/128, ks = (tid/32)%4, n = tid%32)
__global__ __launch_bounds__(512) void stepK(const float* __restrict__ W_hh,
                                             const float* __restrict__ b_hh, int t) {
    __shared__ float part[3][4][4][32];   // [gate][jl][ks][n]
    int tid = threadIdx.x;
    int n = tid & 31, ks = (tid >> 5) & 3, jl = tid >> 7;
    int j = blockIdx.x * 4 + jl;

    const float* hp = g_Hst + (size_t)t * (HID * NB);   // [k][n]
    int kb = ks * 128;
    const float* wr = W_hh + (size_t)j * 512 + kb;
    const float* wz = wr + 512 * 512;
    const float* wn = wz + 512 * 512;
    const float* hb = hp + kb * NB;

    float ar = 0.f, az = 0.f, an = 0.f;
#pragma unroll 8
    for (int k = 0; k < 128; k += 4) {
        float4 r4 = *(const float4*)(wr + k);
        float4 z4 = *(const float4*)(wz + k);
        float4 n4 = *(const float4*)(wn + k);
        float h0 = hb[(k + 0) * NB + n];
        float h1 = hb[(k + 1) * NB + n];
        float h2 = hb[(k + 2) * NB + n];
        float h3 = hb[(k + 3) * NB + n];
        ar = fmaf(r4.x, h0, fmaf(r4.y, h1, fmaf(r4.z, h2, fmaf(r4.w, h3, ar))));
        az = fmaf(z4.x, h0, fmaf(z4.y, h1, fmaf(z4.z, h2, fmaf(z4.w, h3, az))));
        an = fmaf(n4.x, h0, fmaf(n4.y, h1, fmaf(n4.z, h2, fmaf(n4.w, h3, an))));
    }
    part[0][jl][ks][n] = ar;
    part[1][jl][ks][n] = az;
    part[2][jl][ks][n] = an;
    __syncthreads();

    if (tid < 128) {
        int jl2 = tid >> 5, n2 = tid & 31;
        int j2 = blockIdx.x * 4 + jl2;
        float hr = part[0][jl2][0][n2] + part[0][jl2][1][n2] + part[0][jl2][2][n2] + part[0][jl2][3][n2] + b_hh[j2];
        float hz = part[1][jl2][0][n2] + part[1][jl2][1][n2] + part[1][jl2][2][n2] + part[1][jl2][3][n2] + b_hh[j2 + 512];
        float hn = part[2][jl2][0][n2] + part[2][jl2][1][n2] + part[2][jl2][2][n2] + part[2][jl2][3][n2] + b_hh[j2 + 1024];

        float gr = g_Git[((size_t)t * 1536 + j2) * NB + n2];
        float gz = g_Git[((size_t)t * 1536 + j2 + 512) * NB + n2];
        float gn = g_Git[((size_t)t * 1536 + j2 + 1024) * NB + n2];

        float rg_ = sigmoidf_(gr + hr);
        float zg  = sigmoidf_(gz + hz);
        float ng  = tanhf(gn + rg_ * hn);
        float hprev = hp[j2 * NB + n2];
        g_Hst[(size_t)(t + 1) * (HID * NB) + j2 * NB + n2] = (1.0f - zg) * ng + zg * hprev;
    }
}

// ---------------- fused emit GEMM + online logsumexp, smem-tiled ----------------
// grid (x = t 0..126, y = vocab tile 0..399); block 64 threads
// block tile: 32 rows (all n of step t) x 128 vocab; thread tile 8 rows x 8 vocab
// A staged DUPLICATED in smem so LDS.128 yields (h,h) f32x2 operands directly.
#define KC 32
__global__ __launch_bounds__(64) void emitK() {
    __shared__ __align__(16) float Ash[KC][64];    // duplicated rows: [k][2n],[2n+1]
    __shared__ __align__(16) float Bsh[KC][VT];
    __shared__ float redm[32][17];
    __shared__ float reds[32][17];

    int t  = blockIdx.x;          // 0..126
    int vt = blockIdx.y;          // 0..399
    int v0 = vt * VT;
    int tid = threadIdx.x;
    int tx = tid & 15;            // vocab group (8 each)
    int ty = tid >> 4;            // row group (8 each)

    const float* hsrc = g_Hst + (size_t)(t + 1) * (HID * NB);  // [k][n], n contiguous
    const float* wsrc = g_Wt_emit + v0;

    ull acc[8][4];
#pragma unroll
    for (int a = 0; a < 8; ++a)
#pragma unroll
        for (int b = 0; b < 4; ++b) acc[a][b] = 0ull;

#pragma unroll 1
    for (int s = 0; s < 512 / KC; ++s) {
        int k0 = s * KC;
        // stage A (duplicated): 32k x 32n unique, 16 per thread
#pragma unroll
        for (int i = tid; i < KC * 32; i += 64) {
            int kk = i >> 5, nn = i & 31;
            float h = hsrc[(k0 + kk) * NB + nn];
            *(float2*)&Ash[kk][2 * nn] = make_float2(h, h);
        }
        // stage B: 32k x 128v = 1024 float4, 16 per thread
#pragma unroll
        for (int i = tid; i < KC * VT / 4; i += 64) {
            int kk = i >> 5, q = i & 31;
            *(float4*)&Bsh[kk][q * 4] = *(const float4*)(wsrc + (size_t)(k0 + kk) * VPAD + q * 4);
        }
        __syncthreads();

#pragma unroll 8
        for (int kk = 0; kk < KC; ++kk) {
            ulonglong2 a01 = *(const ulonglong2*)&Ash[kk][ty * 16];
            ulonglong2 a23 = *(const ulonglong2*)&Ash[kk][ty * 16 + 4];
            ulonglong2 a45 = *(const ulonglong2*)&Ash[kk][ty * 16 + 8];
            ulonglong2 a67 = *(const ulonglong2*)&Ash[kk][ty * 16 + 12];
            ulonglong2 b01 = *(const ulonglong2*)&Bsh[kk][tx * 8];
            ulonglong2 b23 = *(const ulonglong2*)&Bsh[kk][tx * 8 + 4];
            ull aa[8] = {a01.x, a01.y, a23.x, a23.y, a45.x, a45.y, a67.x, a67.y};
            ull bb[4] = {b01.x, b01.y, b23.x, b23.y};
#pragma unroll
            for (int ri = 0; ri < 8; ++ri) {
#pragma unroll
                for (int p = 0; p < 4; ++p) ffma2(acc[ri][p], aa[ri], bb[p]);
            }
        }
        __syncthreads();
    }

    // epilogue: branchless online logsumexp per row over this thread's 8 vocab
    const float* bp = g_bpad + v0 + tx * 8;
    float m[8], ssum[8];
#pragma unroll
    for (int ri = 0; ri < 8; ++ri) { m[ri] = -1e30f; ssum[ri] = 0.0f; }
#pragma unroll
    for (int ri = 0; ri < 8; ++ri) {
#pragma unroll
        for (int p = 0; p < 4; ++p) {
            float2 l = unpack2(acc[ri][p]);
            float x0 = l.x + bp[2 * p];
            float x1 = l.y + bp[2 * p + 1];
            float m2 = fmaxf(m[ri], fmaxf(x0, x1));
            ssum[ri] = ssum[ri] * __expf(m[ri] - m2) + __expf(x0 - m2) + __expf(x1 - m2);
            m[ri] = m2;
        }
    }
#pragma unroll
    for (int ri = 0; ri < 8; ++ri) {
        redm[ty * 8 + ri][tx] = m[ri];
        reds[ty * 8 + ri][tx] = ssum[ri];
    }
    __syncthreads();
    if (tid < 32) {
        float M = -1e30f, S = 0.0f;
#pragma unroll
        for (int x = 0; x < 16; ++x) lse_combine(M, S, redm[tid][x], reds[tid][x]);
        size_t r = (size_t)t * NB + tid;            // row = t*32 + n
        g_Pm[(size_t)vt * NROWS + r] = M;
        g_Ps[(size_t)vt * NROWS + r] = S;
    }
}

// ---------------- target logits: one warp per (t, n) row ----------------
__global__ void tlogK(const int* __restrict__ words,
                      const float* __restrict__ emit_W,
                      const float* __restrict__ emit_b) {
    int gtid = blockIdx.x * blockDim.x + threadIdx.x;
    int warp = gtid >> 5;
    int lane = threadIdx.x & 31;
    if (warp >= NROWS) return;
    int t = warp >> 5, n = warp & 31;
    int tgt = words[n * TT + t + 1];
    const float* h = g_Hst + (size_t)(t + 1) * (HID * NB);
    const float* w = emit_W + (size_t)tgt * 512;
    float s = 0.0f;
    for (int k = lane; k < 512; k += 32) s += h[k * NB + n] * w[k];
#pragma unroll
    for (int o = 16; o; o >>= 1) s += __shfl_xor_sync(0xffffffffu, s, o);
    if (lane == 0) g_Tlog[warp] = s + emit_b[tgt];
}

// ---------------- finalize ----------------
__global__ void finK(float* __restrict__ out) {
    int n = blockIdx.x;
    int tid = threadIdx.x;
    __shared__ float sh[128];
    float v = 0.0f;
    if (tid < NSTEP) {
        size_t r = (size_t)tid * NB + n;
        float M = -1e30f, S = 0.0f;
        for (int c = 0; c < NVT; ++c) lse_combine(M, S, g_Pm[(size_t)c * NROWS + r], g_Ps[(size_t)c * NROWS + r]);
        v = g_Tlog[r] - (M + logf(S));
    }
    sh[tid] = v;
    __syncthreads();
    for (int o = 64; o; o >>= 1) { if (tid < o) sh[tid] += sh[tid + o]; __syncthreads(); }
    if (tid == 0) out[n] = sh[0] / (float)NSTEP;
}

// ---------------- h_final ----------------
__global__ void hfinK(float* __restrict__ out) {
    int idx = blockIdx.x * blockDim.x + threadIdx.x;  // 0..16383
    int n = idx >> 9, k = idx & 511;
    out[32 + idx] = g_Hst[(size_t)127 * (HID * NB) + k * NB + n];
}

// ---------------- launch ----------------
extern "C" void kernel_launch(void* const* d_in, const int* in_sizes, int n_in,
                              void* d_out, int out_size) {
    const int*   words  = (const int*)d_in[0];
    const float* h0     = (const float*)d_in[1];
    const float* embW   = (const float*)d_in[2];
    const float* W_ih   = (const float*)d_in[3];
    const float* W_hh   = (const float*)d_in[4];
    const float* b_ih   = (const float*)d_in[5];
    const float* b_hh   = (const float*)d_in[6];
    const float* emit_W = (const float*)d_in[7];
    const float* emit_b = (const float*)d_in[8];
    float* out = (float*)d_out;

    transposeK<<<dim3(VPAD / 32, 16), dim3(32, 8)>>>(emit_W, V_VOCAB, VPAD, 0);
    transposeK<<<dim3(1536 / 32, 16), dim3(32, 8)>>>(W_ih, 1536, 1536, 1);
    initK<<<64, 256>>>(h0);
    bpadK<<<(VPAD + 255) / 256, 256>>>(emit_b);

    giK<<<dim3(3, 254), 256>>>(words, embW, b_ih);

    for (int t = 0; t < NSTEP; ++t)
        stepK<<<128, 512>>>(W_hh, b_hh, t);

    emitK<<<dim3(NSTEP, NVT), 64>>>();

    tlogK<<<508, 256>>>(words, emit_W, emit_b);
    finK<<<32, 128>>>(out);
    hfinK<<<64, 256>>>(out);
}

// round 4
// speedup vs baseline: 3.4630x; 1.5861x over previous
#include <cuda_runtime.h>
#include <cuda_bf16.h>
#include <math.h>

typedef unsigned long long ull;
typedef unsigned int uint32;

#define V_VOCAB 50257
#define VP2     50432          // 197 tiles * 256
#define NVT2    197
#define HID     512
#define NB      32
#define TT      128
#define NSTEP   127
#define NROWS   4064
#define RPAD    4096           // 32 row tiles * 128

// ---------------- static device scratch ----------------
__device__ __align__(16) float g_Wt_ih[512 * 1536];               // W_ih transposed [k][j]
__device__ __align__(16) float g_Git[(size_t)NSTEP * 1536 * NB];  // gi, [t][j][n]
__device__ __align__(16) float g_Hst[128 * HID * NB];             // hidden states [t][k][n]
__device__ __align__(16) float g_bpad[VP2];                       // emit_b padded with -1e30
__device__ __align__(16) __nv_bfloat16 g_Whi[(size_t)VP2 * 512];  // emit_W hi, [v][k]
__device__ __align__(16) __nv_bfloat16 g_Wlo[(size_t)VP2 * 512];  // emit_W lo
__device__ __align__(16) __nv_bfloat16 g_Ahi[RPAD * 512];         // h states hi, [row=t*32+n][k]
__device__ __align__(16) __nv_bfloat16 g_Alo[RPAD * 512];
__device__ float g_Pm[(size_t)NVT2 * RPAD];                       // per-vocab-tile max
__device__ float g_Ps[(size_t)NVT2 * RPAD];                       // per-vocab-tile sumexp
__device__ float g_Tlog[NROWS];                                   // target logits

__device__ __forceinline__ float sigmoidf_(float x) { return 1.0f / (1.0f + expf(-x)); }

__device__ __forceinline__ void lse_combine(float& M, float& S, float m2, float s2) {
    if (m2 > M) { S = S * expf(M - m2) + s2; M = m2; }
    else        { S += s2 * expf(m2 - M); }
}

// ---------------- f32x2 helpers (giK) ----------------
__device__ __forceinline__ ull pack2(float lo, float hi) {
    ull r; asm("mov.b64 %0, {%1, %2};" : "=l"(r) : "f"(lo), "f"(hi)); return r;
}
__device__ __forceinline__ float2 unpack2(ull v) {
    float2 f; asm("mov.b64 {%0, %1}, %2;" : "=f"(f.x), "=f"(f.y) : "l"(v)); return f;
}
__device__ __forceinline__ void ffma2(ull& acc, ull a, ull b) {
    asm("fma.rn.f32x2 %0, %1, %2, %0;" : "+l"(acc) : "l"(a), "l"(b));
}

// ---------------- tensor-core helpers ----------------
__device__ __forceinline__ uint32 smem_u32(const void* p) {
    return (uint32)__cvta_generic_to_shared(p);
}
#define LDSM4(R, addr) asm volatile( \
    "ldmatrix.sync.aligned.m8n8.x4.shared.b16 {%0,%1,%2,%3}, [%4];" \
    : "=r"((R)[0]), "=r"((R)[1]), "=r"((R)[2]), "=r"((R)[3]) : "r"(addr))
#define MMA_BF16(D, A, B0, B1) asm volatile( \
    "mma.sync.aligned.m16n8k16.row.col.f32.bf16.bf16.f32 " \
    "{%0,%1,%2,%3}, {%4,%5,%6,%7}, {%8,%9}, {%0,%1,%2,%3};" \
    : "+f"((D)[0]), "+f"((D)[1]), "+f"((D)[2]), "+f"((D)[3]) \
    : "r"((A)[0]), "r"((A)[1]), "r"((A)[2]), "r"((A)[3]), "r"(B0), "r"(B1))

// ---------------- transpose (W_ih only): src[r][c] -> dst[c][r] ----------------
__global__ void transposeK(const float* __restrict__ src) {
    float* dst = g_Wt_ih;
    __shared__ float tile[32][33];
    int r0 = blockIdx.x * 32, c0 = blockIdx.y * 32;
    int tx = threadIdx.x, ty = threadIdx.y;
#pragma unroll
    for (int dy = 0; dy < 32; dy += 8)
        tile[ty + dy][tx] = src[(size_t)(r0 + ty + dy) * 512 + c0 + tx];
    __syncthreads();
#pragma unroll
    for (int dy = 0; dy < 32; dy += 8)
        dst[(size_t)(c0 + ty + dy) * 1536 + r0 + tx] = tile[tx][ty + dy];
}

// ---------------- init + padded bias + weight conversion ----------------
__global__ void initK(const float* __restrict__ h0) {
    int idx = blockIdx.x * blockDim.x + threadIdx.x;   // 0..16383
    int n = idx >> 9, k = idx & 511;
    g_Hst[k * NB + n] = h0[idx];
}
__global__ void bpadK(const float* __restrict__ emit_b) {
    int v = blockIdx.x * blockDim.x + threadIdx.x;
    if (v < VP2) g_bpad[v] = (v < V_VOCAB) ? emit_b[v] : -1e30f;
}
__global__ void convW(const float* __restrict__ emit_W) {
    size_t idx = (size_t)blockIdx.x * blockDim.x + threadIdx.x;
    size_t total = (size_t)VP2 * 512;
    if (idx >= total) return;
    int v = (int)(idx >> 9);
    float x = (v < V_VOCAB) ? emit_W[idx - (size_t)(v - v) * 0 + 0] : 0.0f;  // idx == v*512+k
    if (v < V_VOCAB) x = emit_W[idx]; else x = 0.0f;
    __nv_bfloat16 hi = __float2bfloat16(x);
    float lo = x - __bfloat162float(hi);
    g_Whi[idx] = hi;
    g_Wlo[idx] = __float2bfloat16(lo);
}
__global__ void convA() {
    int idx = blockIdx.x * blockDim.x + threadIdx.x;   // over RPAD*512
    if (idx >= RPAD * 512) return;
    int r = idx >> 9, k = idx & 511;
    float x = 0.0f;
    if (r < NROWS) {
        int t = r >> 5, n = r & 31;
        x = g_Hst[(size_t)(t + 1) * (HID * NB) + k * NB + n];
    }
    __nv_bfloat16 hi = __float2bfloat16(x);
    float lo = x - __bfloat162float(hi);
    g_Ahi[idx] = hi;
    g_Alo[idx] = __float2bfloat16(lo);
}

// ---------------- gi GEMM (unchanged) ----------------
__global__ __launch_bounds__(256) void giK(const int* __restrict__ words,
                                           const float* __restrict__ embW,
                                           const float* __restrict__ b_ih) {
    int jc = blockIdx.x, rg = blockIdx.y;
    int tid = threadIdx.x, tx = tid & 63, ty = tid >> 6;
    __shared__ float ash[16 * 514];
    int rbase = rg * 16;
    for (int idx = tid; idx < 8192; idx += 256) {
        int i = idx >> 9, k = idx & 511;
        int r = rbase + i;
        int w = words[(r & 31) * TT + (r >> 5)];
        ash[i * 514 + k] = embW[(size_t)w * 512 + k];
    }
    __syncthreads();

    int j0 = jc * 512 + tx * 8;
    ull acc[4][4];
#pragma unroll
    for (int a = 0; a < 4; ++a)
#pragma unroll
        for (int b = 0; b < 4; ++b) acc[a][b] = 0ull;

    const float* wp = g_Wt_ih + j0;
    int rb = ty * 4;
#pragma unroll 4
    for (int k = 0; k < 512; ++k) {
        float4 wa = *(const float4*)(wp);
        float4 wb = *(const float4*)(wp + 4);
        wp += 1536;
        ull b0 = pack2(wa.x, wa.y), b1 = pack2(wa.z, wa.w);
        ull b2 = pack2(wb.x, wb.y), b3 = pack2(wb.z, wb.w);
#pragma unroll
        for (int ri = 0; ri < 4; ++ri) {
            float h = ash[(rb + ri) * 514 + k];
            ull a2 = pack2(h, h);
            ffma2(acc[ri][0], a2, b0);
            ffma2(acc[ri][1], a2, b1);
            ffma2(acc[ri][2], a2, b2);
            ffma2(acc[ri][3], a2, b3);
        }
    }

    int t = rbase >> 5;
#pragma unroll
    for (int ri = 0; ri < 4; ++ri) {
        int r = rbase + rb + ri;
        int n = r & 31;
#pragma unroll
        for (int p = 0; p < 4; ++p) {
            float2 l = unpack2(acc[ri][p]);
            int j = j0 + 2 * p;
            g_Git[((size_t)t * 1536 + j) * NB + n]     = l.x + b_ih[j];
            g_Git[((size_t)t * 1536 + j + 1) * NB + n] = l.y + b_ih[j + 1];
        }
    }
}

// ---------------- sequential GRU step, split-k x4 (unchanged) ----------------
__global__ __launch_bounds__(512) void stepK(const float* __restrict__ W_hh,
                                             const float* __restrict__ b_hh, int t) {
    __shared__ float part[3][4][4][32];
    int tid = threadIdx.x;
    int n = tid & 31, ks = (tid >> 5) & 3, jl = tid >> 7;
    int j = blockIdx.x * 4 + jl;

    const float* hp = g_Hst + (size_t)t * (HID * NB);
    int kb = ks * 128;
    const float* wr = W_hh + (size_t)j * 512 + kb;
    const float* wz = wr + 512 * 512;
    const float* wn = wz + 512 * 512;
    const float* hb = hp + kb * NB;

    float ar = 0.f, az = 0.f, an = 0.f;
#pragma unroll 8
    for (int k = 0; k < 128; k += 4) {
        float4 r4 = *(const float4*)(wr + k);
        float4 z4 = *(const float4*)(wz + k);
        float4 n4 = *(const float4*)(wn + k);
        float h0 = hb[(k + 0) * NB + n];
        float h1 = hb[(k + 1) * NB + n];
        float h2 = hb[(k + 2) * NB + n];
        float h3 = hb[(k + 3) * NB + n];
        ar = fmaf(r4.x, h0, fmaf(r4.y, h1, fmaf(r4.z, h2, fmaf(r4.w, h3, ar))));
        az = fmaf(z4.x, h0, fmaf(z4.y, h1, fmaf(z4.z, h2, fmaf(z4.w, h3, az))));
        an = fmaf(n4.x, h0, fmaf(n4.y, h1, fmaf(n4.z, h2, fmaf(n4.w, h3, an))));
    }
    part[0][jl][ks][n] = ar;
    part[1][jl][ks][n] = az;
    part[2][jl][ks][n] = an;
    __syncthreads();

    if (tid < 128) {
        int jl2 = tid >> 5, n2 = tid & 31;
        int j2 = blockIdx.x * 4 + jl2;
        float hr = part[0][jl2][0][n2] + part[0][jl2][1][n2] + part[0][jl2][2][n2] + part[0][jl2][3][n2] + b_hh[j2];
        float hz = part[1][jl2][0][n2] + part[1][jl2][1][n2] + part[1][jl2][2][n2] + part[1][jl2][3][n2] + b_hh[j2 + 512];
        float hn = part[2][jl2][0][n2] + part[2][jl2][1][n2] + part[2][jl2][2][n2] + part[2][jl2][3][n2] + b_hh[j2 + 1024];

        float gr = g_Git[((size_t)t * 1536 + j2) * NB + n2];
        float gz = g_Git[((size_t)t * 1536 + j2 + 512) * NB + n2];
        float gn = g_Git[((size_t)t * 1536 + j2 + 1024) * NB + n2];

        float rg_ = sigmoidf_(gr + hr);
        float zg  = sigmoidf_(gz + hz);
        float ng  = tanhf(gn + rg_ * hn);
        float hprev = hp[j2 * NB + n2];
        g_Hst[(size_t)(t + 1) * (HID * NB) + j2 * NB + n2] = (1.0f - zg) * ng + zg * hprev;
    }
}

// ---------------- tensor-core emit GEMM + fused logsumexp ----------------
// grid (x = row tile 0..31, y = vocab tile 0..196); block 512 = 16 warps
// block tile: 128 rows x 256 vocab, K=512 in 32 stages of 16
// warp (mq = w&3, nq = w>>2): 32 rows x 64 vocab; split-bf16: hi*hi + hi*lo + lo*hi
__global__ __launch_bounds__(512, 1) void emitTC() {
    __shared__ __nv_bfloat16 Ash[2][128][24];   // [hi/lo][row][k], 48B row stride (conflict-free ldmatrix)
    __shared__ __nv_bfloat16 Bsh[2][256][24];   // [hi/lo][vocab][k]
    __shared__ float redm[128][4];
    __shared__ float reds[128][4];
    __shared__ float bsh[256];

    int bt = blockIdx.x, vt = blockIdx.y;
    int ro = bt * 128, vo = vt * 256;
    int tid = threadIdx.x, lane = tid & 31, w = tid >> 5;
    int mq = w & 3, nq = w >> 2;
    int rowBase = mq * 32, colBase = nq * 64;

    if (tid < 256) bsh[tid] = g_bpad[vo + tid];

    // ldmatrix per-lane addresses (fixed, single-buffered smem)
    int g  = lane >> 2, tg = lane & 3;
    int ar = (lane & 7) + ((lane >> 3) & 1) * 8;
    int ac = ((lane >> 4) & 1) * 8;
    int br = (lane & 7) + ((lane >> 4) & 1) * 8;
    int bc = ((lane >> 3) & 1) * 8;
    uint32 aAddr[2][2], bAddr[4][2];
#pragma unroll
    for (int mt = 0; mt < 2; ++mt)
#pragma unroll
        for (int hl = 0; hl < 2; ++hl)
            aAddr[mt][hl] = smem_u32(&Ash[hl][rowBase + mt * 16 + ar][ac]);
#pragma unroll
    for (int np = 0; np < 4; ++np)
#pragma unroll
        for (int hl = 0; hl < 2; ++hl)
            bAddr[np][hl] = smem_u32(&Bsh[hl][colBase + np * 16 + br][bc]);

    float acc[2][8][4];
#pragma unroll
    for (int mt = 0; mt < 2; ++mt)
#pragma unroll
        for (int nt = 0; nt < 8; ++nt)
#pragma unroll
            for (int c = 0; c < 4; ++c) acc[mt][nt][c] = 0.0f;

    const __nv_bfloat16* aSrc[2] = { g_Ahi, g_Alo };
    const __nv_bfloat16* bSrc[2] = { g_Whi, g_Wlo };

#pragma unroll 1
    for (int s = 0; s < 32; ++s) {
        int k0 = s * 16;
        // stage A: 2 hl x 128 rows x 4 uint2 (16 bf16/row)
#pragma unroll
        for (int i = tid; i < 1024; i += 512) {
            int hl = i >> 9, rr = (i >> 2) & 127, q = i & 3;
            uint2 v2 = *(const uint2*)(aSrc[hl] + (size_t)(ro + rr) * 512 + k0 + q * 4);
            *(uint2*)&Ash[hl][rr][q * 4] = v2;
        }
        // stage B: 2 hl x 256 rows x 4 uint2
#pragma unroll
        for (int i = tid; i < 2048; i += 512) {
            int hl = i >> 10, rr = (i >> 2) & 255, q = i & 3;
            uint2 v2 = *(const uint2*)(bSrc[hl] + (size_t)(vo + rr) * 512 + k0 + q * 4);
            *(uint2*)&Bsh[hl][rr][q * 4] = v2;
        }
        __syncthreads();

        uint32 af[2][2][4];
#pragma unroll
        for (int mt = 0; mt < 2; ++mt) {
            LDSM4(af[mt][0], aAddr[mt][0]);
            LDSM4(af[mt][1], aAddr[mt][1]);
        }
#pragma unroll
        for (int np = 0; np < 4; ++np) {
            uint32 bh[4], bl[4];
            LDSM4(bh, bAddr[np][0]);
            LDSM4(bl, bAddr[np][1]);
#pragma unroll
            for (int mt = 0; mt < 2; ++mt) {
#pragma unroll
                for (int sub = 0; sub < 2; ++sub) {
                    float* d = acc[mt][2 * np + sub];
                    MMA_BF16(d, af[mt][0], bh[2 * sub], bh[2 * sub + 1]);   // hi*hi
                    MMA_BF16(d, af[mt][0], bl[2 * sub], bl[2 * sub + 1]);   // hi*lo
                    MMA_BF16(d, af[mt][1], bh[2 * sub], bh[2 * sub + 1]);   // lo*hi
                }
            }
        }
        __syncthreads();
    }

    // epilogue: per-row max + sumexp over this thread's 16 cols, then tg / warp / block reduce
#pragma unroll
    for (int mt = 0; mt < 2; ++mt) {
#pragma unroll
        for (int h = 0; h < 2; ++h) {
            float x[16], m = -1e30f;
#pragma unroll
            for (int nt = 0; nt < 8; ++nt) {
#pragma unroll
                for (int c = 0; c < 2; ++c) {
                    float v = acc[mt][nt][2 * h + c] + bsh[colBase + nt * 8 + 2 * tg + c];
                    x[nt * 2 + c] = v;
                    m = fmaxf(m, v);
                }
            }
            float ssum = 0.0f;
#pragma unroll
            for (int i = 0; i < 16; ++i) ssum += __expf(x[i] - m);
            // reduce across the 4 tg lanes of this row
#pragma unroll
            for (int o = 1; o <= 2; o <<= 1) {
                float m2 = __shfl_xor_sync(0xffffffffu, m, o);
                float s2 = __shfl_xor_sync(0xffffffffu, ssum, o);
                lse_combine(m, ssum, m2, s2);
            }
            if (tg == 0) {
                int rl = rowBase + mt * 16 + g + h * 8;
                redm[rl][nq] = m;
                reds[rl][nq] = ssum;
            }
        }
    }
    __syncthreads();
    if (tid < 128) {
        float M = -1e30f, S = 0.0f;
#pragma unroll
        for (int q = 0; q < 4; ++q) lse_combine(M, S, redm[tid][q], reds[tid][q]);
        int grow = ro + tid;
        if (grow < NROWS) {
            g_Pm[(size_t)vt * RPAD + grow] = M;
            g_Ps[(size_t)vt * RPAD + grow] = S;
        }
    }
}

// ---------------- target logits ----------------
__global__ void tlogK(const int* __restrict__ words,
                      const float* __restrict__ emit_W,
                      const float* __restrict__ emit_b) {
    int gtid = blockIdx.x * blockDim.x + threadIdx.x;
    int warp = gtid >> 5;
    int lane = threadIdx.x & 31;
    if (warp >= NROWS) return;
    int t = warp >> 5, n = warp & 31;
    int tgt = words[n * TT + t + 1];
    const float* h = g_Hst + (size_t)(t + 1) * (HID * NB);
    const float* wv = emit_W + (size_t)tgt * 512;
    float s = 0.0f;
    for (int k = lane; k < 512; k += 32) s += h[k * NB + n] * wv[k];
#pragma unroll
    for (int o = 16; o; o >>= 1) s += __shfl_xor_sync(0xffffffffu, s, o);
    if (lane == 0) g_Tlog[warp] = s + emit_b[tgt];
}

// ---------------- finalize ----------------
__global__ void finK(float* __restrict__ out) {
    int n = blockIdx.x;
    int tid = threadIdx.x;
    __shared__ float sh[128];
    float v = 0.0f;
    if (tid < NSTEP) {
        int r = tid * NB + n;
        float M = -1e30f, S = 0.0f;
        for (int c = 0; c < NVT2; ++c)
            lse_combine(M, S, g_Pm[(size_t)c * RPAD + r], g_Ps[(size_t)c * RPAD + r]);
        v = g_Tlog[r] - (M + logf(S));
    }
    sh[tid] = v;
    __syncthreads();
    for (int o = 64; o; o >>= 1) { if (tid < o) sh[tid] += sh[tid + o]; __syncthreads(); }
    if (tid == 0) out[n] = sh[0] / (float)NSTEP;
}

// ---------------- h_final ----------------
__global__ void hfinK(float* __restrict__ out) {
    int idx = blockIdx.x * blockDim.x + threadIdx.x;
    int n = idx >> 9, k = idx & 511;
    out[32 + idx] = g_Hst[(size_t)127 * (HID * NB) + k * NB + n];
}

// ---------------- launch ----------------
extern "C" void kernel_launch(void* const* d_in, const int* in_sizes, int n_in,
                              void* d_out, int out_size) {
    const int*   words  = (const int*)d_in[0];
    const float* h0     = (const float*)d_in[1];
    const float* embW   = (const float*)d_in[2];
    const float* W_ih   = (const float*)d_in[3];
    const float* W_hh   = (const float*)d_in[4];
    const float* b_ih   = (const float*)d_in[5];
    const float* b_hh   = (const float*)d_in[6];
    const float* emit_W = (const float*)d_in[7];
    const float* emit_b = (const float*)d_in[8];
    float* out = (float*)d_out;

    // prep (independent)
    convW<<<(int)(((size_t)VP2 * 512 + 255) / 256), 256>>>(emit_W);
    bpadK<<<(VP2 + 255) / 256, 256>>>(emit_b);
    transposeK<<<dim3(1536 / 32, 16), dim3(32, 8)>>>(W_ih);
    initK<<<64, 256>>>(h0);

    // input-gate projections
    giK<<<dim3(3, 254), 256>>>(words, embW, b_ih);

    // sequential GRU recurrence
    for (int t = 0; t < NSTEP; ++t)
        stepK<<<128, 512>>>(W_hh, b_hh, t);

    // convert hidden states to split-bf16
    convA<<<(RPAD * 512 + 255) / 256, 256>>>();

    // tensor-core emit GEMM + logsumexp
    emitTC<<<dim3(32, NVT2), 512>>>();

    tlogK<<<508, 256>>>(words, emit_W, emit_b);
    finK<<<32, 128>>>(out);
    hfinK<<<64, 256>>>(out);
}

// round 8
// speedup vs baseline: 4.3989x; 1.2703x over previous
#include <cuda_runtime.h>
#include <cuda_bf16.h>
#include <math.h>

typedef unsigned long long ull;
typedef unsigned int uint32;

#define V_VOCAB 50257
#define VP2     50432          // 197 tiles * 256
#define NVT2    197
#define HID     512
#define NB      32
#define TT      128
#define NSTEP   127
#define NROWS   4064
#define RPAD    4096           // 32 row tiles * 128
#define NBLK    128            // persistent GRU blocks

// emit tile: M=128 x N=256, K=512 in 16 stages of 32
#define TM      128
#define TN      256
#define KC2     32
#define NSTG    16
#define ABLK    10240          // 128 rows * 80B (padded image block, one hl, one kchunk)
#define BBLK    20480          // 256 rows * 80B
#define STGB    40960          // Ahi + Alo + B per stage
#define DYNB    (2 * STGB)     // 81920

// ---------------- static device scratch ----------------
__device__ __align__(16) float g_Wt_ih[512 * 1536];               // W_ih transposed [k][j]
__device__ __align__(16) float g_Git[(size_t)NSTEP * 1536 * NB];  // gi, [t][j][n]
__device__ __align__(16) float g_Hst[128 * HID * NB];             // hidden states [t][k][n]
__device__ __align__(16) float g_bpad[VP2];                       // emit_b padded with -1e30
// B image: [vt][kc 16][vrow 256][40 bf16] — byte-exact smem tile, 80B rows
__device__ __align__(16) __nv_bfloat16 g_Wimg[(size_t)NVT2 * 16 * 256 * 40];
// A image: [bt 32][hl 2][kc 16][mrow 128][40 bf16]
__device__ __align__(16) __nv_bfloat16 g_Aimg[(size_t)32 * 2 * 16 * 128 * 40];
__device__ float g_Pm[(size_t)NVT2 * RPAD];
__device__ float g_Ps[(size_t)NVT2 * RPAD];
__device__ float g_Tlog[NROWS];
__device__ unsigned int g_cnt = 0;   // grid barrier arrivals (self-resetting)
__device__ unsigned int g_gen = 0;   // grid barrier generation (monotonic)

__device__ __forceinline__ float sigmoidf_(float x) { return 1.0f / (1.0f + expf(-x)); }

__device__ __forceinline__ void lse_combine(float& M, float& S, float m2, float s2) {
    if (m2 > M) { S = S * expf(M - m2) + s2; M = m2; }
    else        { S += s2 * expf(m2 - M); }
}

// fast exp for x <= 0 on the FMA pipe (deg-5, rint-centered; rel err ~4e-7)
__device__ __forceinline__ float fexp(float x) {
    x = fmaxf(x, -20.0f);
    float t = x * 1.4426950408889634f;
    float fi = rintf(t);
    float f = t - fi;                      // [-0.5, 0.5]
    float p = 0.0013333558f;
    p = fmaf(p, f, 0.0096181291f);
    p = fmaf(p, f, 0.0555041087f);
    p = fmaf(p, f, 0.2402265070f);
    p = fmaf(p, f, 0.6931471806f);
    p = fmaf(p, f, 1.0f);
    int e = (int)fi;
    float s = __int_as_float((e + 127) << 23);
    return p * s;
}

// ---------------- f32x2 helpers (giK) ----------------
__device__ __forceinline__ ull pack2(float lo, float hi) {
    ull r; asm("mov.b64 %0, {%1, %2};" : "=l"(r) : "f"(lo), "f"(hi)); return r;
}
__device__ __forceinline__ float2 unpack2(ull v) {
    float2 f; asm("mov.b64 {%0, %1}, %2;" : "=f"(f.x), "=f"(f.y) : "l"(v)); return f;
}
__device__ __forceinline__ void ffma2(ull& acc, ull a, ull b) {
    asm("fma.rn.f32x2 %0, %1, %2, %0;" : "+l"(acc) : "l"(a), "l"(b));
}

// ---------------- mma / bulk helpers (sm_90 baseline features only) ----------------
__device__ __forceinline__ uint32 smem_u32(const void* p) {
    return (uint32)__cvta_generic_to_shared(p);
}
#define LDSM4(R, addr) asm volatile( \
    "ldmatrix.sync.aligned.m8n8.x4.shared.b16 {%0,%1,%2,%3}, [%4];" \
    : "=r"((R)[0]), "=r"((R)[1]), "=r"((R)[2]), "=r"((R)[3]) : "r"(addr))
#define MMA_BF16(D, A, B0, B1) asm volatile( \
    "mma.sync.aligned.m16n8k16.row.col.f32.bf16.bf16.f32 " \
    "{%0,%1,%2,%3}, {%4,%5,%6,%7}, {%8,%9}, {%0,%1,%2,%3};" \
    : "+f"((D)[0]), "+f"((D)[1]), "+f"((D)[2]), "+f"((D)[3]) \
    : "r"((A)[0]), "r"((A)[1]), "r"((A)[2]), "r"((A)[3]), "r"(B0), "r"(B1))
#define MBAR_INIT(mb, cnt) asm volatile( \
    "mbarrier.init.shared.b64 [%0], %1;" :: "r"(mb), "r"((uint32)(cnt)) : "memory")
#define EXPECT_TX(mb, bytes) asm volatile( \
    "mbarrier.arrive.expect_tx.shared.b64 _, [%0], %1;" :: "r"(mb), "r"((uint32)(bytes)) : "memory")
#define BULK(dst, src, bytes, mb) asm volatile( \
    "cp.async.bulk.shared::cluster.global.mbarrier::complete_tx::bytes [%0], [%1], %2, [%3];" \
    :: "r"(dst), "l"(src), "r"((uint32)(bytes)), "r"(mb) : "memory")
#define MBAR_WAIT(mb, par) do { \
    uint32 _mb = (mb); uint32 _p = (par); uint32 _done; \
    asm volatile("{\n\t.reg .pred p;\n\t" \
        "mbarrier.try_wait.parity.acquire.cta.shared::cta.b64 p, [%1], %2;\n\t" \
        "selp.b32 %0, 1, 0, p;\n\t}" : "=r"(_done) : "r"(_mb), "r"(_p) : "memory"); \
    if (!_done) { \
        asm volatile("{\n\t.reg .pred P1;\n\t" \
            "WL_%=:\n\t" \
            "mbarrier.try_wait.parity.acquire.cta.shared::cta.b64 P1, [%0], %1, 0x989680;\n\t" \
            "@P1 bra.uni WD_%=;\n\t" \
            "bra.uni WL_%=;\n\t" \
            "WD_%=:\n\t}" :: "r"(_mb), "r"(_p) : "memory"); \
    } \
} while (0)

// ---------------- prep kernels ----------------
__global__ void transposeK(const float* __restrict__ src) {
    float* dst = g_Wt_ih;
    __shared__ float tile[32][33];
    int r0 = blockIdx.x * 32, c0 = blockIdx.y * 32;
    int tx = threadIdx.x, ty = threadIdx.y;
#pragma unroll
    for (int dy = 0; dy < 32; dy += 8)
        tile[ty + dy][tx] = src[(size_t)(r0 + ty + dy) * 512 + c0 + tx];
    __syncthreads();
#pragma unroll
    for (int dy = 0; dy < 32; dy += 8)
        dst[(size_t)(c0 + ty + dy) * 1536 + r0 + tx] = tile[tx][ty + dy];
}

__global__ void initK(const float* __restrict__ h0) {
    int idx = blockIdx.x * blockDim.x + threadIdx.x;
    int n = idx >> 9, k = idx & 511;
    g_Hst[k * NB + n] = h0[idx];
}
__global__ void bpadK(const float* __restrict__ emit_b) {
    int v = blockIdx.x * blockDim.x + threadIdx.x;
    if (v < VP2) g_bpad[v] = (v < V_VOCAB) ? emit_b[v] : -1e30f;
}
// build B image: [vt][kc][vr][40] (c>=32 pad -> 0)
__global__ void convWimg(const float* __restrict__ emit_W) {
    size_t idx = (size_t)blockIdx.x * blockDim.x + threadIdx.x;
    if (idx >= (size_t)NVT2 * 16 * 256 * 40) return;
    int c  = (int)(idx % 40);
    int vr = (int)((idx / 40) % 256);
    int kc = (int)((idx / (40 * 256)) % 16);
    int vt = (int)(idx / (40 * 256 * 16));
    int v = vt * 256 + vr, k = kc * 32 + c;
    float x = (c < 32 && v < V_VOCAB) ? emit_W[(size_t)v * 512 + k] : 0.0f;
    g_Wimg[idx] = __float2bfloat16(x);
}

// ---------------- gi GEMM ----------------
__global__ __launch_bounds__(256) void giK(const int* __restrict__ words,
                                           const float* __restrict__ embW,
                                           const float* __restrict__ b_ih) {
    int jc = blockIdx.x, rg = blockIdx.y;
    int tid = threadIdx.x, tx = tid & 63, ty = tid >> 6;
    __shared__ float ash[16 * 514];
    int rbase = rg * 16;
    for (int idx = tid; idx < 8192; idx += 256) {
        int i = idx >> 9, k = idx & 511;
        int r = rbase + i;
        int w = words[(r & 31) * TT + (r >> 5)];
        ash[i * 514 + k] = embW[(size_t)w * 512 + k];
    }
    __syncthreads();

    int j0 = jc * 512 + tx * 8;
    ull acc[4][4];
#pragma unroll
    for (int a = 0; a < 4; ++a)
#pragma unroll
        for (int b = 0; b < 4; ++b) acc[a][b] = 0ull;

    const float* wp = g_Wt_ih + j0;
    int rb = ty * 4;
#pragma unroll 4
    for (int k = 0; k < 512; ++k) {
        float4 wa = *(const float4*)(wp);
        float4 wb = *(const float4*)(wp + 4);
        wp += 1536;
        ull b0 = pack2(wa.x, wa.y), b1 = pack2(wa.z, wa.w);
        ull b2 = pack2(wb.x, wb.y), b3 = pack2(wb.z, wb.w);
#pragma unroll
        for (int ri = 0; ri < 4; ++ri) {
            float h = ash[(rb + ri) * 514 + k];
            ull a2 = pack2(h, h);
            ffma2(acc[ri][0], a2, b0);
            ffma2(acc[ri][1], a2, b1);
            ffma2(acc[ri][2], a2, b2);
            ffma2(acc[ri][3], a2, b3);
        }
    }

    int t = rbase >> 5;
#pragma unroll
    for (int ri = 0; ri < 4; ++ri) {
        int r = rbase + rb + ri;
        int n = r & 31;
#pragma unroll
        for (int p = 0; p < 4; ++p) {
            float2 l = unpack2(acc[ri][p]);
            int j = j0 + 2 * p;
            g_Git[((size_t)t * 1536 + j) * NB + n]     = l.x + b_ih[j];
            g_Git[((size_t)t * 1536 + j + 1) * NB + n] = l.y + b_ih[j + 1];
        }
    }
}

// ---------------- persistent GRU: 127 steps, software grid barrier ----------------
__global__ __launch_bounds__(512) void gruPersist(const float* __restrict__ W_hh,
                                                  const float* __restrict__ b_hh) {
    __shared__ float part[3][4][4][32];
    int tid = threadIdx.x;
    int n = tid & 31, ks = (tid >> 5) & 3, jl = tid >> 7;
    int bx = blockIdx.x;
    int j = bx * 4 + jl;
    unsigned int mygen = g_gen;

    int kb = ks * 128;
    const float* wr = W_hh + (size_t)j * 512 + kb;
    const float* wz = wr + 512 * 512;
    const float* wn = wz + 512 * 512;

    for (int t = 0; t < NSTEP; ++t) {
        const float* hp = g_Hst + (size_t)t * (HID * NB);
        const float* hb = hp + kb * NB;

        float ar = 0.f, az = 0.f, an = 0.f;
#pragma unroll 8
        for (int k = 0; k < 128; k += 4) {
            float4 r4 = *(const float4*)(wr + k);
            float4 z4 = *(const float4*)(wz + k);
            float4 n4 = *(const float4*)(wn + k);
            float h0 = hb[(k + 0) * NB + n];
            float h1 = hb[(k + 1) * NB + n];
            float h2 = hb[(k + 2) * NB + n];
            float h3 = hb[(k + 3) * NB + n];
            ar = fmaf(r4.x, h0, fmaf(r4.y, h1, fmaf(r4.z, h2, fmaf(r4.w, h3, ar))));
            az = fmaf(z4.x, h0, fmaf(z4.y, h1, fmaf(z4.z, h2, fmaf(z4.w, h3, az))));
            an = fmaf(n4.x, h0, fmaf(n4.y, h1, fmaf(n4.z, h2, fmaf(n4.w, h3, an))));
        }
        part[0][jl][ks][n] = ar;
        part[1][jl][ks][n] = az;
        part[2][jl][ks][n] = an;
        __syncthreads();

        if (tid < 128) {
            int jl2 = tid >> 5, n2 = tid & 31;
            int j2 = bx * 4 + jl2;
            float hr = part[0][jl2][0][n2] + part[0][jl2][1][n2] + part[0][jl2][2][n2] + part[0][jl2][3][n2] + b_hh[j2];
            float hz = part[1][jl2][0][n2] + part[1][jl2][1][n2] + part[1][jl2][2][n2] + part[1][jl2][3][n2] + b_hh[j2 + 512];
            float hn = part[2][jl2][0][n2] + part[2][jl2][1][n2] + part[2][jl2][2][n2] + part[2][jl2][3][n2] + b_hh[j2 + 1024];

            float gr = g_Git[((size_t)t * 1536 + j2) * NB + n2];
            float gz = g_Git[((size_t)t * 1536 + j2 + 512) * NB + n2];
            float gn = g_Git[((size_t)t * 1536 + j2 + 1024) * NB + n2];

            float rg_ = sigmoidf_(gr + hr);
            float zg  = sigmoidf_(gz + hz);
            float ng  = tanhf(gn + rg_ * hn);
            float hprev = hp[j2 * NB + n2];
            float hval = (1.0f - zg) * ng + zg * hprev;
            g_Hst[(size_t)(t + 1) * (HID * NB) + j2 * NB + n2] = hval;

            // split-bf16 A image write (hi + lo)
            int r = t * 32 + n2;
            int btI = r >> 7, mr = r & 127, kc = j2 >> 5, cc = j2 & 31;
            __nv_bfloat16 hi = __float2bfloat16(hval);
            float lo = hval - __bfloat162float(hi);
            size_t baseI = (size_t)((btI * 2) * 16 + kc) * 5120 + (size_t)mr * 40 + cc;
            g_Aimg[baseI] = hi;
            g_Aimg[baseI + (size_t)16 * 5120] = __float2bfloat16(lo);
        }

        // grid barrier (release all writes, sense-reversing, replay-safe)
        __threadfence();
        __syncthreads();
        if (tid == 0) {
            unsigned int old = atomicAdd(&g_cnt, 1);
            if (old == NBLK - 1) {
                *((volatile unsigned int*)&g_cnt) = 0;
                __threadfence();
                atomicAdd(&g_gen, 1);
            } else {
                unsigned int cur;
                do {
                    asm volatile("ld.acquire.gpu.u32 %0, [%1];" : "=r"(cur) : "l"(&g_gen));
                } while (cur == mygen);
            }
        }
        mygen++;
        __syncthreads();
    }
}

// ---------------- emit GEMM (mma.sync bf16, 2-term split-A) + fused logsumexp ----------------
// grid (bt 0..31, vt 0..196), 512 threads / 16 warps; CTA tile 128x256, K in 16 stages of 32.
// Staging: 3 cp.async.bulk per stage (Ahi/Alo/B images are byte-exact smem tiles), double-buffered.
__global__ __launch_bounds__(512, 1) void emitMMA() {
    extern __shared__ __align__(128) char dsm[];
    __shared__ float bsh[TN];
    __shared__ float redm[128][4], reds[128][4];
    __shared__ __align__(8) ull s_mbar[2];

    int tid = threadIdx.x, lane = tid & 31, w = tid >> 5;
    int mq = w & 3, nq = w >> 2;
    int rowBase = mq * 32, colBase = nq * 64;
    int bt = blockIdx.x, vt = blockIdx.y;
    int ro = bt * TM, vo = vt * TN;

    uint32 base = smem_u32(dsm);
    if (tid == 0) { MBAR_INIT(smem_u32(&s_mbar[0]), 1); MBAR_INIT(smem_u32(&s_mbar[1]), 1); }
    if (tid < TN) bsh[tid] = g_bpad[vo + tid];
    __syncthreads();
    uint32 mb[2] = { smem_u32(&s_mbar[0]), smem_u32(&s_mbar[1]) };
    int ph[2] = { 0, 0 };

    const char* srcAhi = (const char*)g_Aimg + (size_t)(bt * 2 + 0) * 16 * ABLK;
    const char* srcAlo = (const char*)g_Aimg + (size_t)(bt * 2 + 1) * 16 * ABLK;
    const char* srcB   = (const char*)g_Wimg + (size_t)vt * 16 * BBLK;

    if (tid == 0) {
        EXPECT_TX(mb[0], STGB);
        BULK(base,             srcAhi, ABLK, mb[0]);
        BULK(base + ABLK,      srcAlo, ABLK, mb[0]);
        BULK(base + 2 * ABLK,  srcB,   BBLK, mb[0]);
    }

    int ar = (lane & 7) + ((lane >> 3) & 1) * 8, ac = ((lane >> 4) & 1) * 8;
    int br = (lane & 7) + ((lane >> 4) & 1) * 8, bc = ((lane >> 3) & 1) * 8;
    uint32 aOff0 = (uint32)((rowBase + ar) * 80 + ac * 2);
    uint32 aOff1 = (uint32)((rowBase + 16 + ar) * 80 + ac * 2);
    uint32 bOffs[4];
#pragma unroll
    for (int np = 0; np < 4; ++np) bOffs[np] = (uint32)((colBase + np * 16 + br) * 80 + bc * 2);

    float acc[2][8][4];
#pragma unroll
    for (int mt = 0; mt < 2; ++mt)
#pragma unroll
        for (int nt = 0; nt < 8; ++nt)
#pragma unroll
            for (int c = 0; c < 4; ++c) acc[mt][nt][c] = 0.0f;

#pragma unroll 1
    for (int s = 0; s < NSTG; ++s) {
        int b = s & 1;
        if (tid == 0 && s + 1 < NSTG) {
            int nb = (s + 1) & 1;
            uint32 nbase = base + (uint32)nb * STGB;
            EXPECT_TX(mb[nb], STGB);
            BULK(nbase,            srcAhi + (size_t)(s + 1) * ABLK, ABLK, mb[nb]);
            BULK(nbase + ABLK,     srcAlo + (size_t)(s + 1) * ABLK, ABLK, mb[nb]);
            BULK(nbase + 2 * ABLK, srcB   + (size_t)(s + 1) * BBLK, BBLK, mb[nb]);
        }
        MBAR_WAIT(mb[b], ph[b]); ph[b] ^= 1;

        uint32 bufA = base + (uint32)b * STGB;
        uint32 bufB = bufA + 2 * ABLK;
#pragma unroll
        for (int kbi = 0; kbi < 2; ++kbi) {
            uint32 ko = (uint32)(kbi * 32);
            uint32 af[2][2][4];
            LDSM4(af[0][0], bufA + aOff0 + ko);
            LDSM4(af[0][1], bufA + ABLK + aOff0 + ko);
            LDSM4(af[1][0], bufA + aOff1 + ko);
            LDSM4(af[1][1], bufA + ABLK + aOff1 + ko);
#pragma unroll
            for (int np = 0; np < 4; ++np) {
                uint32 bb[4];
                LDSM4(bb, bufB + bOffs[np] + ko);
#pragma unroll
                for (int mt = 0; mt < 2; ++mt) {
#pragma unroll
                    for (int sub = 0; sub < 2; ++sub) {
                        float* d = acc[mt][2 * np + sub];
                        MMA_BF16(d, af[mt][0], bb[2 * sub], bb[2 * sub + 1]);   // hiA * B
                        MMA_BF16(d, af[mt][1], bb[2 * sub], bb[2 * sub + 1]);   // loA * B
                    }
                }
            }
        }
        __syncthreads();
    }

    // epilogue: bias + per-row max/sumexp (poly exp on FMA pipe), lane/warp/block reduce
    int g = lane >> 2, tg = lane & 3;
#pragma unroll
    for (int mt = 0; mt < 2; ++mt) {
#pragma unroll
        for (int h = 0; h < 2; ++h) {
            float x[16], m = -1e30f;
#pragma unroll
            for (int nt = 0; nt < 8; ++nt) {
#pragma unroll
                for (int c = 0; c < 2; ++c) {
                    float v = acc[mt][nt][2 * h + c] + bsh[colBase + nt * 8 + 2 * tg + c];
                    x[nt * 2 + c] = v;
                    m = fmaxf(m, v);
                }
            }
            float ssum = 0.0f;
#pragma unroll
            for (int i = 0; i < 16; ++i) ssum += fexp(x[i] - m);
#pragma unroll
            for (int o = 1; o <= 2; o <<= 1) {
                float m2 = __shfl_xor_sync(0xffffffffu, m, o);
                float s2 = __shfl_xor_sync(0xffffffffu, ssum, o);
                lse_combine(m, ssum, m2, s2);
            }
            if (tg == 0) {
                int rl = rowBase + mt * 16 + g + h * 8;
                redm[rl][nq] = m;
                reds[rl][nq] = ssum;
            }
        }
    }
    __syncthreads();
    if (tid < 128) {
        float M = -1e30f, S = 0.0f;
#pragma unroll
        for (int q = 0; q < 4; ++q) lse_combine(M, S, redm[tid][q], reds[tid][q]);
        int row = ro + tid;
        g_Pm[(size_t)vt * RPAD + row] = M;
        g_Ps[(size_t)vt * RPAD + row] = S;
    }
}

// ---------------- target logits ----------------
__global__ void tlogK(const int* __restrict__ words,
                      const float* __restrict__ emit_W,
                      const float* __restrict__ emit_b) {
    int gtid = blockIdx.x * blockDim.x + threadIdx.x;
    int warp = gtid >> 5;
    int lane = threadIdx.x & 31;
    if (warp >= NROWS) return;
    int t = warp >> 5, n = warp & 31;
    int tgt = words[n * TT + t + 1];
    const float* h = g_Hst + (size_t)(t + 1) * (HID * NB);
    const float* wv = emit_W + (size_t)tgt * 512;
    float s = 0.0f;
    for (int k = lane; k < 512; k += 32) s += h[k * NB + n] * wv[k];
#pragma unroll
    for (int o = 16; o; o >>= 1) s += __shfl_xor_sync(0xffffffffu, s, o);
    if (lane == 0) g_Tlog[warp] = s + emit_b[tgt];
}

// ---------------- finalize ----------------
__global__ void finK(float* __restrict__ out) {
    int n = blockIdx.x;
    int tid = threadIdx.x;
    __shared__ float sh[128];
    float v = 0.0f;
    if (tid < NSTEP) {
        int r = tid * NB + n;
        float M = -1e30f, S = 0.0f;
        for (int c = 0; c < NVT2; ++c)
            lse_combine(M, S, g_Pm[(size_t)c * RPAD + r], g_Ps[(size_t)c * RPAD + r]);
        v = g_Tlog[r] - (M + logf(S));
    }
    sh[tid] = v;
    __syncthreads();
    for (int o = 64; o; o >>= 1) { if (tid < o) sh[tid] += sh[tid + o]; __syncthreads(); }
    if (tid == 0) out[n] = sh[0] / (float)NSTEP;
}

// ---------------- h_final ----------------
__global__ void hfinK(float* __restrict__ out) {
    int idx = blockIdx.x * blockDim.x + threadIdx.x;
    int n = idx >> 9, k = idx & 511;
    out[32 + idx] = g_Hst[(size_t)127 * (HID * NB) + k * NB + n];
}

// ---------------- launch ----------------
extern "C" void kernel_launch(void* const* d_in, const int* in_sizes, int n_in,
                              void* d_out, int out_size) {
    const int*   words  = (const int*)d_in[0];
    const float* h0     = (const float*)d_in[1];
    const float* embW   = (const float*)d_in[2];
    const float* W_ih   = (const float*)d_in[3];
    const float* W_hh   = (const float*)d_in[4];
    const float* b_ih   = (const float*)d_in[5];
    const float* b_hh   = (const float*)d_in[6];
    const float* emit_W = (const float*)d_in[7];
    const float* emit_b = (const float*)d_in[8];
    float* out = (float*)d_out;

    static int configured = 0;
    if (!configured) {
        cudaFuncSetAttribute(emitMMA, cudaFuncAttributeMaxDynamicSharedMemorySize, DYNB);
        configured = 1;
    }

    // prep (independent)
    {
        size_t total = (size_t)NVT2 * 16 * 256 * 40;
        convWimg<<<(int)((total + 255) / 256), 256>>>(emit_W);
    }
    bpadK<<<(VP2 + 255) / 256, 256>>>(emit_b);
    transposeK<<<dim3(1536 / 32, 16), dim3(32, 8)>>>(W_ih);
    initK<<<64, 256>>>(h0);

    // input-gate projections
    giK<<<dim3(3, 254), 256>>>(words, embW, b_ih);

    // persistent GRU recurrence (fuses split-bf16 A-image conversion)
    gruPersist<<<NBLK, 512>>>(W_hh, b_hh);

    // emit GEMM + logsumexp
    emitMMA<<<dim3(32, NVT2), 512, DYNB>>>();

    tlogK<<<508, 256>>>(words, emit_W, emit_b);
    finK<<<32, 128>>>(out);
    hfinK<<<64, 256>>>(out);
}

// round 9
// speedup vs baseline: 4.8583x; 1.1044x over previous
#include <cuda_runtime.h>
#include <cuda_bf16.h>
#include <math.h>

typedef unsigned long long ull;
typedef unsigned int uint32;

#define V_VOCAB 50257
#define VP2     50432          // 197 tiles * 256
#define NVT2    197
#define HID     512
#define NB      32
#define TT      128
#define NSTEP   127
#define NROWS   4064
#define RPAD    4096           // 32 row tiles * 128
#define NBLK    128            // persistent GRU blocks

// emit tile: M=128 x N=256, K=512 in 16 stages of 32; 4-deep bulk ring
#define TM      128
#define TN      256
#define NSTG    16
#define ABLK    10240          // 128 rows * 80B
#define BBLK    20480          // 256 rows * 80B
#define STG1    (ABLK + BBLK)  // 30720
#define NRING   4
#define DYNB    (NRING * STG1) // 122880

// ---------------- static device scratch ----------------
__device__ __align__(16) float g_Wt_ih[512 * 1536];               // W_ih transposed [k][j]
__device__ __align__(16) float g_Git[(size_t)NSTEP * 1536 * NB];  // gi, [t][j][n]
__device__ __align__(16) float g_Hst[128 * HID * NB];             // hidden states [t][k][n]
__device__ __align__(16) float g_bpad[VP2];                       // emit_b padded with -1e30
// B image: [vt][kc 16][vrow 256][40 bf16] — byte-exact smem tile, 80B rows
__device__ __align__(16) __nv_bfloat16 g_Wimg[(size_t)NVT2 * 16 * 256 * 40];
// A image: [bt 32][kc 16][mrow 128][40 bf16] (hi only)
__device__ __align__(16) __nv_bfloat16 g_Aimg[(size_t)32 * 16 * 128 * 40];
__device__ float g_Pm[(size_t)NVT2 * RPAD];
__device__ float g_Ps[(size_t)NVT2 * RPAD];
__device__ float g_Tlog[NROWS];
__device__ unsigned int g_cnt = 0;   // grid barrier arrivals (self-resetting)
__device__ unsigned int g_gen = 0;   // grid barrier generation (monotonic)

__device__ __forceinline__ float sigmoidf_(float x) { return 1.0f / (1.0f + expf(-x)); }

__device__ __forceinline__ void lse_combine(float& M, float& S, float m2, float s2) {
    if (m2 > M) { S = S * expf(M - m2) + s2; M = m2; }
    else        { S += s2 * expf(m2 - M); }
}

// fast exp for x <= 0 on the FMA pipe (deg-5, rint-centered; rel err ~4e-7)
__device__ __forceinline__ float fexp(float x) {
    x = fmaxf(x, -20.0f);
    float t = x * 1.4426950408889634f;
    float fi = rintf(t);
    float f = t - fi;
    float p = 0.0013333558f;
    p = fmaf(p, f, 0.0096181291f);
    p = fmaf(p, f, 0.0555041087f);
    p = fmaf(p, f, 0.2402265070f);
    p = fmaf(p, f, 0.6931471806f);
    p = fmaf(p, f, 1.0f);
    int e = (int)fi;
    float s = __int_as_float((e + 127) << 23);
    return p * s;
}

// ---------------- f32x2 helpers (giK) ----------------
__device__ __forceinline__ ull pack2(float lo, float hi) {
    ull r; asm("mov.b64 %0, {%1, %2};" : "=l"(r) : "f"(lo), "f"(hi)); return r;
}
__device__ __forceinline__ float2 unpack2(ull v) {
    float2 f; asm("mov.b64 {%0, %1}, %2;" : "=f"(f.x), "=f"(f.y) : "l"(v)); return f;
}
__device__ __forceinline__ void ffma2(ull& acc, ull a, ull b) {
    asm("fma.rn.f32x2 %0, %1, %2, %0;" : "+l"(acc) : "l"(a), "l"(b));
}

// ---------------- mma / bulk helpers ----------------
__device__ __forceinline__ uint32 smem_u32(const void* p) {
    return (uint32)__cvta_generic_to_shared(p);
}
#define LDSM4(R, addr) asm volatile( \
    "ldmatrix.sync.aligned.m8n8.x4.shared.b16 {%0,%1,%2,%3}, [%4];" \
    : "=r"((R)[0]), "=r"((R)[1]), "=r"((R)[2]), "=r"((R)[3]) : "r"(addr))
#define MMA_BF16(D, A, B0, B1) asm volatile( \
    "mma.sync.aligned.m16n8k16.row.col.f32.bf16.bf16.f32 " \
    "{%0,%1,%2,%3}, {%4,%5,%6,%7}, {%8,%9}, {%0,%1,%2,%3};" \
    : "+f"((D)[0]), "+f"((D)[1]), "+f"((D)[2]), "+f"((D)[3]) \
    : "r"((A)[0]), "r"((A)[1]), "r"((A)[2]), "r"((A)[3]), "r"(B0), "r"(B1))
#define MBAR_INIT(mb, cnt) asm volatile( \
    "mbarrier.init.shared.b64 [%0], %1;" :: "r"(mb), "r"((uint32)(cnt)) : "memory")
#define EXPECT_TX(mb, bytes) asm volatile( \
    "mbarrier.arrive.expect_tx.shared.b64 _, [%0], %1;" :: "r"(mb), "r"((uint32)(bytes)) : "memory")
#define BULK(dst, src, bytes, mb) asm volatile( \
    "cp.async.bulk.shared::cluster.global.mbarrier::complete_tx::bytes [%0], [%1], %2, [%3];" \
    :: "r"(dst), "l"(src), "r"((uint32)(bytes)), "r"(mb) : "memory")
#define MBAR_WAIT(mb, par) do { \
    uint32 _mb = (mb); uint32 _p = (par); uint32 _done; \
    asm volatile("{\n\t.reg .pred p;\n\t" \
        "mbarrier.try_wait.parity.acquire.cta.shared::cta.b64 p, [%1], %2;\n\t" \
        "selp.b32 %0, 1, 0, p;\n\t}" : "=r"(_done) : "r"(_mb), "r"(_p) : "memory"); \
    if (!_done) { \
        asm volatile("{\n\t.reg .pred P1;\n\t" \
            "WL_%=:\n\t" \
            "mbarrier.try_wait.parity.acquire.cta.shared::cta.b64 P1, [%0], %1, 0x989680;\n\t" \
            "@P1 bra.uni WD_%=;\n\t" \
            "bra.uni WL_%=;\n\t" \
            "WD_%=:\n\t}" :: "r"(_mb), "r"(_p) : "memory"); \
    } \
} while (0)

// ---------------- prep kernels ----------------
__global__ void transposeK(const float* __restrict__ src) {
    float* dst = g_Wt_ih;
    __shared__ float tile[32][33];
    int r0 = blockIdx.x * 32, c0 = blockIdx.y * 32;
    int tx = threadIdx.x, ty = threadIdx.y;
#pragma unroll
    for (int dy = 0; dy < 32; dy += 8)
        tile[ty + dy][tx] = src[(size_t)(r0 + ty + dy) * 512 + c0 + tx];
    __syncthreads();
#pragma unroll
    for (int dy = 0; dy < 32; dy += 8)
        dst[(size_t)(c0 + ty + dy) * 1536 + r0 + tx] = tile[tx][ty + dy];
}

__global__ void initK(const float* __restrict__ h0) {
    int idx = blockIdx.x * blockDim.x + threadIdx.x;
    int n = idx >> 9, k = idx & 511;
    g_Hst[k * NB + n] = h0[idx];
}
__global__ void bpadK(const float* __restrict__ emit_b) {
    int v = blockIdx.x * blockDim.x + threadIdx.x;
    if (v < VP2) g_bpad[v] = (v < V_VOCAB) ? emit_b[v] : -1e30f;
}
// build B image: [vt][kc][vr][40] (c>=32 pad -> 0)
__global__ void convWimg(const float* __restrict__ emit_W) {
    size_t idx = (size_t)blockIdx.x * blockDim.x + threadIdx.x;
    if (idx >= (size_t)NVT2 * 16 * 256 * 40) return;
    int c  = (int)(idx % 40);
    int vr = (int)((idx / 40) % 256);
    int kc = (int)((idx / (40 * 256)) % 16);
    int vt = (int)(idx / (40 * 256 * 16));
    int v = vt * 256 + vr, k = kc * 32 + c;
    float x = (c < 32 && v < V_VOCAB) ? emit_W[(size_t)v * 512 + k] : 0.0f;
    g_Wimg[idx] = __float2bfloat16(x);
}

// ---------------- gi GEMM ----------------
__global__ __launch_bounds__(256) void giK(const int* __restrict__ words,
                                           const float* __restrict__ embW,
                                           const float* __restrict__ b_ih) {
    int jc = blockIdx.x, rg = blockIdx.y;
    int tid = threadIdx.x, tx = tid & 63, ty = tid >> 6;
    __shared__ float ash[16 * 514];
    int rbase = rg * 16;
    for (int idx = tid; idx < 8192; idx += 256) {
        int i = idx >> 9, k = idx & 511;
        int r = rbase + i;
        int w = words[(r & 31) * TT + (r >> 5)];
        ash[i * 514 + k] = embW[(size_t)w * 512 + k];
    }
    __syncthreads();

    int j0 = jc * 512 + tx * 8;
    ull acc[4][4];
#pragma unroll
    for (int a = 0; a < 4; ++a)
#pragma unroll
        for (int b = 0; b < 4; ++b) acc[a][b] = 0ull;

    const float* wp = g_Wt_ih + j0;
    int rb = ty * 4;
#pragma unroll 4
    for (int k = 0; k < 512; ++k) {
        float4 wa = *(const float4*)(wp);
        float4 wb = *(const float4*)(wp + 4);
        wp += 1536;
        ull b0 = pack2(wa.x, wa.y), b1 = pack2(wa.z, wa.w);
        ull b2 = pack2(wb.x, wb.y), b3 = pack2(wb.z, wb.w);
#pragma unroll
        for (int ri = 0; ri < 4; ++ri) {
            float h = ash[(rb + ri) * 514 + k];
            ull a2 = pack2(h, h);
            ffma2(acc[ri][0], a2, b0);
            ffma2(acc[ri][1], a2, b1);
            ffma2(acc[ri][2], a2, b2);
            ffma2(acc[ri][3], a2, b3);
        }
    }

    int t = rbase >> 5;
#pragma unroll
    for (int ri = 0; ri < 4; ++ri) {
        int r = rbase + rb + ri;
        int n = r & 31;
#pragma unroll
        for (int p = 0; p < 4; ++p) {
            float2 l = unpack2(acc[ri][p]);
            int j = j0 + 2 * p;
            g_Git[((size_t)t * 1536 + j) * NB + n]     = l.x + b_ih[j];
            g_Git[((size_t)t * 1536 + j + 1) * NB + n] = l.y + b_ih[j + 1];
        }
    }
}

// ---------------- persistent GRU: 127 steps, cheap grid barrier ----------------
__global__ __launch_bounds__(512) void gruPersist(const float* __restrict__ W_hh,
                                                  const float* __restrict__ b_hh) {
    __shared__ float part[3][4][4][32];
    int tid = threadIdx.x;
    int n = tid & 31, ks = (tid >> 5) & 3, jl = tid >> 7;
    int bx = blockIdx.x;
    int j = bx * 4 + jl;
    unsigned int mygen = g_gen;

    int kb = ks * 128;
    const float* wr = W_hh + (size_t)j * 512 + kb;
    const float* wz = wr + 512 * 512;
    const float* wn = wz + 512 * 512;

    for (int t = 0; t < NSTEP; ++t) {
        const float* hp = g_Hst + (size_t)t * (HID * NB);
        const float* hb = hp + kb * NB;

        float ar = 0.f, az = 0.f, an = 0.f;
#pragma unroll 8
        for (int k = 0; k < 128; k += 4) {
            float4 r4 = *(const float4*)(wr + k);
            float4 z4 = *(const float4*)(wz + k);
            float4 n4 = *(const float4*)(wn + k);
            float h0 = hb[(k + 0) * NB + n];
            float h1 = hb[(k + 1) * NB + n];
            float h2 = hb[(k + 2) * NB + n];
            float h3 = hb[(k + 3) * NB + n];
            ar = fmaf(r4.x, h0, fmaf(r4.y, h1, fmaf(r4.z, h2, fmaf(r4.w, h3, ar))));
            az = fmaf(z4.x, h0, fmaf(z4.y, h1, fmaf(z4.z, h2, fmaf(z4.w, h3, az))));
            an = fmaf(n4.x, h0, fmaf(n4.y, h1, fmaf(n4.z, h2, fmaf(n4.w, h3, an))));
        }
        part[0][jl][ks][n] = ar;
        part[1][jl][ks][n] = az;
        part[2][jl][ks][n] = an;
        __syncthreads();

        if (tid < 128) {
            int jl2 = tid >> 5, n2 = tid & 31;
            int j2 = bx * 4 + jl2;
            float hr = part[0][jl2][0][n2] + part[0][jl2][1][n2] + part[0][jl2][2][n2] + part[0][jl2][3][n2] + b_hh[j2];
            float hz = part[1][jl2][0][n2] + part[1][jl2][1][n2] + part[1][jl2][2][n2] + part[1][jl2][3][n2] + b_hh[j2 + 512];
            float hn = part[2][jl2][0][n2] + part[2][jl2][1][n2] + part[2][jl2][2][n2] + part[2][jl2][3][n2] + b_hh[j2 + 1024];

            float gr = g_Git[((size_t)t * 1536 + j2) * NB + n2];
            float gz = g_Git[((size_t)t * 1536 + j2 + 512) * NB + n2];
            float gn = g_Git[((size_t)t * 1536 + j2 + 1024) * NB + n2];

            float rg_ = sigmoidf_(gr + hr);
            float zg  = sigmoidf_(gz + hz);
            float ng  = tanhf(gn + rg_ * hn);
            float hprev = hp[j2 * NB + n2];
            float hval = (1.0f - zg) * ng + zg * hprev;
            g_Hst[(size_t)(t + 1) * (HID * NB) + j2 * NB + n2] = hval;

            // bf16 A image write (hi only)
            int r = t * 32 + n2;
            int btI = r >> 7, mr = r & 127, kc = j2 >> 5, cc = j2 & 31;
            g_Aimg[(size_t)(btI * 16 + kc) * 5120 + (size_t)mr * 40 + cc] = __float2bfloat16(hval);
        }

        // grid barrier: single release fence by arriving thread only
        __syncthreads();
        if (tid == 0) {
            __threadfence();
            unsigned int old = atomicAdd(&g_cnt, 1);
            if (old == NBLK - 1) {
                *((volatile unsigned int*)&g_cnt) = 0;
                __threadfence();
                atomicAdd(&g_gen, 1);
            } else {
                unsigned int cur;
                do {
                    asm volatile("ld.acquire.gpu.u32 %0, [%1];" : "=r"(cur) : "l"(&g_gen));
                } while (cur == mygen);
            }
        }
        mygen++;
        __syncthreads();
    }
}

// ---------------- emit GEMM (pure bf16 mma.sync) + fused logsumexp ----------------
// grid (bt 0..31, vt 0..196), 512 threads / 16 warps; CTA tile 128x256, K in 16 stages of 32.
// 4-deep cp.async.bulk ring (A and B images are byte-exact smem tiles).
__global__ __launch_bounds__(512, 1) void emitMMA() {
    extern __shared__ __align__(128) char dsm[];
    __shared__ float bsh[TN];
    __shared__ float redm[128][4], reds[128][4];
    __shared__ __align__(8) ull s_mbar[NRING];

    int tid = threadIdx.x, lane = tid & 31, w = tid >> 5;
    int mq = w & 3, nq = w >> 2;
    int rowBase = mq * 32, colBase = nq * 64;
    int bt = blockIdx.x, vt = blockIdx.y;
    int ro = bt * TM, vo = vt * TN;

    uint32 base = smem_u32(dsm);
    if (tid == 0) {
#pragma unroll
        for (int i = 0; i < NRING; ++i) MBAR_INIT(smem_u32(&s_mbar[i]), 1);
    }
    if (tid < TN) bsh[tid] = g_bpad[vo + tid];
    __syncthreads();
    uint32 mb[NRING];
#pragma unroll
    for (int i = 0; i < NRING; ++i) mb[i] = smem_u32(&s_mbar[i]);

    const char* srcA = (const char*)g_Aimg + (size_t)bt * 16 * ABLK;
    const char* srcB = (const char*)g_Wimg + (size_t)vt * 16 * BBLK;

    // prologue: issue stages 0..2
    if (tid == 0) {
#pragma unroll
        for (int q = 0; q < NRING - 1; ++q) {
            uint32 qb = base + (uint32)q * STG1;
            EXPECT_TX(mb[q], STG1);
            BULK(qb,        srcA + (size_t)q * ABLK, ABLK, mb[q]);
            BULK(qb + ABLK, srcB + (size_t)q * BBLK, BBLK, mb[q]);
        }
    }

    int ar = (lane & 7) + ((lane >> 3) & 1) * 8, ac = ((lane >> 4) & 1) * 8;
    int br = (lane & 7) + ((lane >> 4) & 1) * 8, bc = ((lane >> 3) & 1) * 8;
    uint32 aOff0 = (uint32)((rowBase + ar) * 80 + ac * 2);
    uint32 aOff1 = (uint32)((rowBase + 16 + ar) * 80 + ac * 2);
    uint32 bOffs[4];
#pragma unroll
    for (int np = 0; np < 4; ++np) bOffs[np] = (uint32)((colBase + np * 16 + br) * 80 + bc * 2);

    float acc[2][8][4];
#pragma unroll
    for (int mt = 0; mt < 2; ++mt)
#pragma unroll
        for (int nt = 0; nt < 8; ++nt)
#pragma unroll
            for (int c = 0; c < 4; ++c) acc[mt][nt][c] = 0.0f;

#pragma unroll 1
    for (int s = 0; s < NSTG; ++s) {
        int slot = s & (NRING - 1);
        if (tid == 0 && s + NRING - 1 < NSTG) {
            int q = s + NRING - 1;
            int qs = q & (NRING - 1);
            uint32 qb = base + (uint32)qs * STG1;
            EXPECT_TX(mb[qs], STG1);
            BULK(qb,        srcA + (size_t)q * ABLK, ABLK, mb[qs]);
            BULK(qb + ABLK, srcB + (size_t)q * BBLK, BBLK, mb[qs]);
        }
        MBAR_WAIT(mb[slot], (s >> 2) & 1);

        uint32 bufA = base + (uint32)slot * STG1;
        uint32 bufB = bufA + ABLK;
#pragma unroll
        for (int kbi = 0; kbi < 2; ++kbi) {
            uint32 ko = (uint32)(kbi * 32);
            uint32 af[2][4];
            LDSM4(af[0], bufA + aOff0 + ko);
            LDSM4(af[1], bufA + aOff1 + ko);
#pragma unroll
            for (int np = 0; np < 4; ++np) {
                uint32 bb[4];
                LDSM4(bb, bufB + bOffs[np] + ko);
#pragma unroll
                for (int mt = 0; mt < 2; ++mt) {
                    MMA_BF16(acc[mt][2 * np + 0], af[mt], bb[0], bb[1]);
                    MMA_BF16(acc[mt][2 * np + 1], af[mt], bb[2], bb[3]);
                }
            }
        }
        __syncthreads();
    }

    // epilogue: bias + per-row max/sumexp (poly exp on FMA pipe), lane/warp/block reduce
    int g = lane >> 2, tg = lane & 3;
#pragma unroll
    for (int mt = 0; mt < 2; ++mt) {
#pragma unroll
        for (int h = 0; h < 2; ++h) {
            float x[16], m = -1e30f;
#pragma unroll
            for (int nt = 0; nt < 8; ++nt) {
#pragma unroll
                for (int c = 0; c < 2; ++c) {
                    float v = acc[mt][nt][2 * h + c] + bsh[colBase + nt * 8 + 2 * tg + c];
                    x[nt * 2 + c] = v;
                    m = fmaxf(m, v);
                }
            }
            float ssum = 0.0f;
#pragma unroll
            for (int i = 0; i < 16; ++i) ssum += fexp(x[i] - m);
#pragma unroll
            for (int o = 1; o <= 2; o <<= 1) {
                float m2 = __shfl_xor_sync(0xffffffffu, m, o);
                float s2 = __shfl_xor_sync(0xffffffffu, ssum, o);
                lse_combine(m, ssum, m2, s2);
            }
            if (tg == 0) {
                int rl = rowBase + mt * 16 + g + h * 8;
                redm[rl][nq] = m;
                reds[rl][nq] = ssum;
            }
        }
    }
    __syncthreads();
    if (tid < 128) {
        float M = -1e30f, S = 0.0f;
#pragma unroll
        for (int q = 0; q < 4; ++q) lse_combine(M, S, redm[tid][q], reds[tid][q]);
        int row = ro + tid;
        g_Pm[(size_t)vt * RPAD + row] = M;
        g_Ps[(size_t)vt * RPAD + row] = S;
    }
}

// ---------------- target logits ----------------
__global__ void tlogK(const int* __restrict__ words,
                      const float* __restrict__ emit_W,
                      const float* __restrict__ emit_b) {
    int gtid = blockIdx.x * blockDim.x + threadIdx.x;
    int warp = gtid >> 5;
    int lane = threadIdx.x & 31;
    if (warp >= NROWS) return;
    int t = warp >> 5, n = warp & 31;
    int tgt = words[n * TT + t + 1];
    const float* h = g_Hst + (size_t)(t + 1) * (HID * NB);
    const float* wv = emit_W + (size_t)tgt * 512;
    float s = 0.0f;
    for (int k = lane; k < 512; k += 32) s += h[k * NB + n] * wv[k];
#pragma unroll
    for (int o = 16; o; o >>= 1) s += __shfl_xor_sync(0xffffffffu, s, o);
    if (lane == 0) g_Tlog[warp] = s + emit_b[tgt];
}

// ---------------- finalize ----------------
__global__ void finK(float* __restrict__ out) {
    int n = blockIdx.x;
    int tid = threadIdx.x;
    __shared__ float sh[128];
    float v = 0.0f;
    if (tid < NSTEP) {
        int r = tid * NB + n;
        float M = -1e30f, S = 0.0f;
        for (int c = 0; c < NVT2; ++c)
            lse_combine(M, S, g_Pm[(size_t)c * RPAD + r], g_Ps[(size_t)c * RPAD + r]);
        v = g_Tlog[r] - (M + logf(S));
    }
    sh[tid] = v;
    __syncthreads();
    for (int o = 64; o; o >>= 1) { if (tid < o) sh[tid] += sh[tid + o]; __syncthreads(); }
    if (tid == 0) out[n] = sh[0] / (float)NSTEP;
}

// ---------------- h_final ----------------
__global__ void hfinK(float* __restrict__ out) {
    int idx = blockIdx.x * blockDim.x + threadIdx.x;
    int n = idx >> 9, k = idx & 511;
    out[32 + idx] = g_Hst[(size_t)127 * (HID * NB) + k * NB + n];
}

// ---------------- launch ----------------
extern "C" void kernel_launch(void* const* d_in, const int* in_sizes, int n_in,
                              void* d_out, int out_size) {
    const int*   words  = (const int*)d_in[0];
    const float* h0     = (const float*)d_in[1];
    const float* embW   = (const float*)d_in[2];
    const float* W_ih   = (const float*)d_in[3];
    const float* W_hh   = (const float*)d_in[4];
    const float* b_ih   = (const float*)d_in[5];
    const float* b_hh   = (const float*)d_in[6];
    const float* emit_W = (const float*)d_in[7];
    const float* emit_b = (const float*)d_in[8];
    float* out = (float*)d_out;

    static int configured = 0;
    if (!configured) {
        cudaFuncSetAttribute(emitMMA, cudaFuncAttributeMaxDynamicSharedMemorySize, DYNB);
        configured = 1;
    }

    // prep (independent)
    {
        size_t total = (size_t)NVT2 * 16 * 256 * 40;
        convWimg<<<(int)((total + 255) / 256), 256>>>(emit_W);
    }
    bpadK<<<(VP2 + 255) / 256, 256>>>(emit_b);
    transposeK<<<dim3(1536 / 32, 16), dim3(32, 8)>>>(W_ih);
    initK<<<64, 256>>>(h0);

    // input-gate projections
    giK<<<dim3(3, 254), 256>>>(words, embW, b_ih);

    // persistent GRU recurrence (fuses bf16 A-image conversion)
    gruPersist<<<NBLK, 512>>>(W_hh, b_hh);

    // emit GEMM + logsumexp
    emitMMA<<<dim3(32, NVT2), 512, DYNB>>>();

    tlogK<<<508, 256>>>(words, emit_W, emit_b);
    finK<<<32, 128>>>(out);
    hfinK<<<64, 256>>>(out);
}